// round 10
// baseline (speedup 1.0000x reference)
#include <cuda_runtime.h>
#include <cuda_bf16.h>
#include <cstdint>
#include <cstddef>

#define D_IN  12544
#define D_HID 1024
#define MAXN  16000

// ---------------- device scratch (allocation-free rule) ----------------
__device__ __align__(1024) __nv_bfloat16 g_Xhi[(size_t)MAXN * D_IN];
__device__ __align__(1024) __nv_bfloat16 g_Xlo[(size_t)MAXN * D_IN];
__device__ __align__(1024) __nv_bfloat16 g_W1hi[(size_t)D_HID * D_IN];  // [N][K]
__device__ __align__(1024) __nv_bfloat16 g_W1lo[(size_t)D_HID * D_IN];
__device__ __align__(1024) __nv_bfloat16 g_W2hi[(size_t)D_HID * D_HID];
__device__ __align__(1024) __nv_bfloat16 g_W2lo[(size_t)D_HID * D_HID];
__device__ __align__(1024) __nv_bfloat16 g_h1hi[(size_t)MAXN * D_HID];
__device__ __align__(1024) __nv_bfloat16 g_h1lo[(size_t)MAXN * D_HID];
__device__ float g_h2[(size_t)MAXN * D_HID];

// ---------------- asm helpers ----------------
__device__ __forceinline__ uint32_t smem_u32(const void* p) {
    uint32_t a;
    asm("{ .reg .u64 t; cvta.to.shared.u64 t, %1; cvt.u32.u64 %0, t; }" : "=r"(a) : "l"(p));
    return a;
}
__device__ __forceinline__ void cp16(uint32_t dst, const void* src) {
    asm volatile("cp.async.cg.shared.global [%0], [%1], 16;" :: "r"(dst), "l"(src));
}
__device__ __forceinline__ void cp_commit() {
    asm volatile("cp.async.commit_group;" ::: "memory");
}
template <int N>
__device__ __forceinline__ void cp_wait() {
    asm volatile("cp.async.wait_group %0;" :: "n"(N) : "memory");
}
__device__ __forceinline__ void ldm_x4(uint32_t* r, uint32_t addr) {
    asm volatile("ldmatrix.sync.aligned.m8n8.x4.shared.b16 {%0,%1,%2,%3}, [%4];"
                 : "=r"(r[0]), "=r"(r[1]), "=r"(r[2]), "=r"(r[3]) : "r"(addr));
}
__device__ __forceinline__ void mma16816(float* c, const uint32_t* a, uint32_t b0, uint32_t b1) {
    asm volatile(
        "mma.sync.aligned.m16n8k16.row.col.f32.bf16.bf16.f32 "
        "{%0,%1,%2,%3}, {%4,%5,%6,%7}, {%8,%9}, {%0,%1,%2,%3};"
        : "+f"(c[0]), "+f"(c[1]), "+f"(c[2]), "+f"(c[3])
        : "r"(a[0]), "r"(a[1]), "r"(a[2]), "r"(a[3]), "r"(b0), "r"(b1));
}

// ---------------- GEMM: C[M,N] = act(A[M,K] @ B[N,K]^T + bias), bf16 hi/lo x3 ----------------
// CTA tile BM=128, BN=128, BK=32. 4-stage cp.async pipeline, prefetch distance 2,
// __syncthreads every 2 iterations (= 4 kk-steps). 16 warps (4 M x 4 N), warp tile 32x32.
// Register double-buffered fragments: LDSM for step u+1 issued during MMAs of step u.
#define LDS       40                    // smem stride in halves (80B) - conflict free
#define TILE_B    (128 * LDS * 2)       // 10240 B per [128][32] bf16 tile
#define OFF_AHI   0
#define OFF_ALO   (TILE_B)
#define OFF_BHI   (2 * TILE_B)
#define OFF_BLO   (3 * TILE_B)
#define STAGE_B   (4 * TILE_B)          // 40960
#define NSTAGE    4
#define SM_TOTAL  (NSTAGE * STAGE_B)    // 163840 -> 1 CTA/SM

__device__ __forceinline__ void load_tile(uint32_t sdst, const __nv_bfloat16* __restrict__ g,
                                          int row0, int K, int k0, int tid)
{
    // 512 threads, 512 x 16B chunks: one chunk per thread
    const char* gb = (const char*)(g + (size_t)row0 * K + k0);
    const int r = tid >> 2;
    const int c = tid & 3;
    cp16(sdst + r * (LDS * 2) + c * 16, gb + (size_t)r * K * 2 + c * 16);
}

template <int WRITE_HILO>
__global__ __launch_bounds__(512, 1)
void gemm_mma_x3(const __nv_bfloat16* __restrict__ Ahi, const __nv_bfloat16* __restrict__ Alo,
                 const __nv_bfloat16* __restrict__ Bhi, const __nv_bfloat16* __restrict__ Blo,
                 const float* __restrict__ bias,
                 __nv_bfloat16* __restrict__ Chi, __nv_bfloat16* __restrict__ Clo,
                 float* __restrict__ Cf,
                 int K, int N)
{
    extern __shared__ char smem[];
    const uint32_t sb = smem_u32(smem);
    const int tid  = threadIdx.x;
    const int wid  = tid >> 5;
    const int lane = tid & 31;
    const int wm   = wid & 3;        // 0..3 (M)
    const int wn   = wid >> 2;       // 0..3 (N)

    const int bm = blockIdx.y * 128;
    const int bn = blockIdx.x * 128;
    const int NK = K / 32;           // even for both GEMMs (392, 32)

    float acc[2][4][4];
#pragma unroll
    for (int mt = 0; mt < 2; mt++)
#pragma unroll
        for (int nb = 0; nb < 4; nb++)
#pragma unroll
            for (int q = 0; q < 4; q++) acc[mt][nb][q] = 0.0f;

    // prologue: prefetch stages 0, 1 (prefetch distance = 2)
#pragma unroll
    for (int s = 0; s < 2; s++) {
        const uint32_t st = sb + s * STAGE_B;
        load_tile(st + OFF_AHI, Ahi, bm, K, s * 32, tid);
        load_tile(st + OFF_ALO, Alo, bm, K, s * 32, tid);
        load_tile(st + OFF_BHI, Bhi, bn, K, s * 32, tid);
        load_tile(st + OFF_BLO, Blo, bn, K, s * 32, tid);
        cp_commit();
    }

    // ldmatrix lane addressing (within-tile offsets, in bytes)
    const uint32_t a_lane_off = ((lane & 15) * LDS + (lane >> 4) * 8) * 2;
    const uint32_t b_lane_off = ((((lane >> 4) * 8) + (lane & 7)) * LDS + (((lane >> 3) & 1) * 8)) * 2;
    const uint32_t a_base_off = (wm * 32) * (LDS * 2);
    const uint32_t b_base_off = (wn * 32) * (LDS * 2);

    // fragment double buffers
    uint32_t ah[2][2][4], al[2][2][4];   // [buf][mt][reg]
    uint32_t bh[2][2][4], bl[2][2][4];   // [buf][pi][reg]

    for (int c2 = 0; c2 < NK; c2 += 2) {
        cp_wait<0>();
        __syncthreads();

        // prefetch stages c2+2, c2+3
#pragma unroll
        for (int d = 2; d < 4; d++) {
            const int pf = c2 + d;
            if (pf < NK) {
                const uint32_t st = sb + (pf & 3) * STAGE_B;
                load_tile(st + OFF_AHI, Ahi, bm, K, pf * 32, tid);
                load_tile(st + OFF_ALO, Alo, bm, K, pf * 32, tid);
                load_tile(st + OFF_BHI, Bhi, bn, K, pf * 32, tid);
                load_tile(st + OFF_BLO, Blo, bn, K, pf * 32, tid);
            }
            cp_commit();
        }

        const uint32_t st0 = sb + (c2 & 3) * STAGE_B;
        const uint32_t st1 = sb + ((c2 + 1) & 3) * STAGE_B;

        // load fragments for step u=0 into buffer 0
        {
            const uint32_t sAh = st0 + OFF_AHI + a_base_off + a_lane_off;
            const uint32_t sAl = st0 + OFF_ALO + a_base_off + a_lane_off;
            const uint32_t sBh = st0 + OFF_BHI + b_base_off + b_lane_off;
            const uint32_t sBl = st0 + OFF_BLO + b_base_off + b_lane_off;
#pragma unroll
            for (int mt = 0; mt < 2; mt++) {
                ldm_x4(ah[0][mt], sAh + mt * 16 * (LDS * 2));
                ldm_x4(al[0][mt], sAl + mt * 16 * (LDS * 2));
            }
#pragma unroll
            for (int pi = 0; pi < 2; pi++) {
                ldm_x4(bh[0][pi], sBh + pi * 16 * (LDS * 2));
                ldm_x4(bl[0][pi], sBl + pi * 16 * (LDS * 2));
            }
        }

        // 4 kk-steps across the two visible stages; prefetch frags for u+1 during MMAs of u
#pragma unroll
        for (int u = 0; u < 4; u++) {
            const int cb = u & 1;
            if (u < 3) {
                const int un = u + 1;
                const int nb_ = un & 1;
                const uint32_t stn = (un < 2) ? st0 : st1;
                const uint32_t ko  = (un & 1) * 32;
                const uint32_t sAh = stn + OFF_AHI + a_base_off + a_lane_off + ko;
                const uint32_t sAl = stn + OFF_ALO + a_base_off + a_lane_off + ko;
                const uint32_t sBh = stn + OFF_BHI + b_base_off + b_lane_off + ko;
                const uint32_t sBl = stn + OFF_BLO + b_base_off + b_lane_off + ko;
#pragma unroll
                for (int mt = 0; mt < 2; mt++) {
                    ldm_x4(ah[nb_][mt], sAh + mt * 16 * (LDS * 2));
                    ldm_x4(al[nb_][mt], sAl + mt * 16 * (LDS * 2));
                }
#pragma unroll
                for (int pi = 0; pi < 2; pi++) {
                    ldm_x4(bh[nb_][pi], sBh + pi * 16 * (LDS * 2));
                    ldm_x4(bl[nb_][pi], sBl + pi * 16 * (LDS * 2));
                }
            }
            // product-major MMAs on current buffer
#pragma unroll
            for (int mt = 0; mt < 2; mt++)
#pragma unroll
                for (int pi = 0; pi < 2; pi++)
#pragma unroll
                    for (int h = 0; h < 2; h++)
                        mma16816(acc[mt][pi * 2 + h], ah[cb][mt], bh[cb][pi][h * 2], bh[cb][pi][h * 2 + 1]);
#pragma unroll
            for (int mt = 0; mt < 2; mt++)
#pragma unroll
                for (int pi = 0; pi < 2; pi++)
#pragma unroll
                    for (int h = 0; h < 2; h++)
                        mma16816(acc[mt][pi * 2 + h], ah[cb][mt], bl[cb][pi][h * 2], bl[cb][pi][h * 2 + 1]);
#pragma unroll
            for (int mt = 0; mt < 2; mt++)
#pragma unroll
                for (int pi = 0; pi < 2; pi++)
#pragma unroll
                    for (int h = 0; h < 2; h++)
                        mma16816(acc[mt][pi * 2 + h], al[cb][mt], bh[cb][pi][h * 2], bh[cb][pi][h * 2 + 1]);
        }
    }

    // ---------------- epilogue: bias + ReLU ----------------
#pragma unroll
    for (int mt = 0; mt < 2; mt++) {
        const int row0 = bm + wm * 32 + mt * 16 + (lane >> 2);
#pragma unroll
        for (int nb = 0; nb < 4; nb++) {
            const int col = bn + wn * 32 + nb * 8 + (lane & 3) * 2;
            const float bx = bias[col];
            const float by = bias[col + 1];
            float y0 = fmaxf(acc[mt][nb][0] + bx, 0.0f);
            float y1 = fmaxf(acc[mt][nb][1] + by, 0.0f);
            float y2 = fmaxf(acc[mt][nb][2] + bx, 0.0f);
            float y3 = fmaxf(acc[mt][nb][3] + by, 0.0f);
            if (WRITE_HILO) {
                __nv_bfloat16 h0 = __float2bfloat16(y0), h1 = __float2bfloat16(y1);
                __nv_bfloat16 h2 = __float2bfloat16(y2), h3 = __float2bfloat16(y3);
                __nv_bfloat16 l0 = __float2bfloat16(y0 - __bfloat162float(h0));
                __nv_bfloat16 l1 = __float2bfloat16(y1 - __bfloat162float(h1));
                __nv_bfloat16 l2 = __float2bfloat16(y2 - __bfloat162float(h2));
                __nv_bfloat16 l3 = __float2bfloat16(y3 - __bfloat162float(h3));
                *(__nv_bfloat162*)(Chi + (size_t)row0 * N + col)       = __nv_bfloat162(h0, h1);
                *(__nv_bfloat162*)(Chi + (size_t)(row0 + 8) * N + col) = __nv_bfloat162(h2, h3);
                *(__nv_bfloat162*)(Clo + (size_t)row0 * N + col)       = __nv_bfloat162(l0, l1);
                *(__nv_bfloat162*)(Clo + (size_t)(row0 + 8) * N + col) = __nv_bfloat162(l2, l3);
            } else {
                *(float2*)(Cf + (size_t)row0 * N + col)       = make_float2(y0, y1);
                *(float2*)(Cf + (size_t)(row0 + 8) * N + col) = make_float2(y2, y3);
            }
        }
    }
}

// ---------------- conversion kernels ----------------
__global__ __launch_bounds__(256)
void split_f32(const float* __restrict__ in, __nv_bfloat16* __restrict__ hi,
               __nv_bfloat16* __restrict__ lo, size_t n4)
{
    size_t i = (size_t)blockIdx.x * blockDim.x + threadIdx.x;
    if (i >= n4) return;
    float4 v = ((const float4*)in)[i];
    __nv_bfloat16 h0 = __float2bfloat16(v.x), h1 = __float2bfloat16(v.y);
    __nv_bfloat16 h2 = __float2bfloat16(v.z), h3 = __float2bfloat16(v.w);
    __nv_bfloat16 l0 = __float2bfloat16(v.x - __bfloat162float(h0));
    __nv_bfloat16 l1 = __float2bfloat16(v.y - __bfloat162float(h1));
    __nv_bfloat16 l2 = __float2bfloat16(v.z - __bfloat162float(h2));
    __nv_bfloat16 l3 = __float2bfloat16(v.w - __bfloat162float(h3));
    ((__nv_bfloat162*)hi)[i * 2 + 0] = __nv_bfloat162(h0, h1);
    ((__nv_bfloat162*)hi)[i * 2 + 1] = __nv_bfloat162(h2, h3);
    ((__nv_bfloat162*)lo)[i * 2 + 0] = __nv_bfloat162(l0, l1);
    ((__nv_bfloat162*)lo)[i * 2 + 1] = __nv_bfloat162(l2, l3);
}

// in: [K][N] fp32 row-major -> out hi/lo: [N][K] bf16 row-major
__global__ __launch_bounds__(256)
void transpose_split(const float* __restrict__ in, __nv_bfloat16* __restrict__ hi,
                     __nv_bfloat16* __restrict__ lo, int K, int N)
{
    __shared__ float t[32][33];
    const int k0 = blockIdx.y * 32;
    const int n0 = blockIdx.x * 32;
    const int tx = threadIdx.x;
    const int ty = threadIdx.y;
#pragma unroll
    for (int r = 0; r < 4; r++) {
        const int k = k0 + ty * 4 + r;
        t[ty * 4 + r][tx] = in[(size_t)k * N + n0 + tx];
    }
    __syncthreads();
#pragma unroll
    for (int r = 0; r < 4; r++) {
        const int n = n0 + ty * 4 + r;
        const float v = t[tx][ty * 4 + r];
        const __nv_bfloat16 h = __float2bfloat16(v);
        const __nv_bfloat16 l = __float2bfloat16(v - __bfloat162float(h));
        hi[(size_t)n * K + k0 + tx] = h;
        lo[(size_t)n * K + k0 + tx] = l;
    }
}

// ---------------- heads ----------------
__global__ __launch_bounds__(256)
void heads_kernel(const float* __restrict__ H,
                  const float* __restrict__ Wc, const float* __restrict__ bc,
                  const float* __restrict__ Wr, const float* __restrict__ br,
                  float* __restrict__ out, int M)
{
    const int warp = (blockIdx.x * blockDim.x + threadIdx.x) >> 5;
    const int lane = threadIdx.x & 31;
    if (warp >= M) return;

    const float* __restrict__ h = H + (size_t)warp * D_HID;
    float acc[16];
#pragma unroll
    for (int c = 0; c < 16; c++) acc[c] = 0.0f;

    for (int k = lane; k < D_HID; k += 32) {
        const float x = h[k];
        const float* wc = Wc + (size_t)k * 4;
#pragma unroll
        for (int c = 0; c < 4; c++) acc[c] = fmaf(x, wc[c], acc[c]);
        const float* wr = Wr + (size_t)k * 12;
#pragma unroll
        for (int c = 0; c < 12; c++) acc[4 + c] = fmaf(x, wr[c], acc[4 + c]);
    }
#pragma unroll
    for (int c = 0; c < 16; c++)
#pragma unroll
        for (int off = 16; off > 0; off >>= 1)
            acc[c] += __shfl_xor_sync(0xffffffffu, acc[c], off);

    if (lane < 4) {
        out[(size_t)warp * 4 + lane] = acc[lane] + bc[lane];
    } else if (lane < 16) {
        out[(size_t)M * 4 + (size_t)warp * 12 + (lane - 4)] = acc[lane] + br[lane - 4];
    }
}

// ---------------- host ----------------
extern "C" void kernel_launch(void* const* d_in, const int* in_sizes, int n_in,
                              void* d_out, int out_size)
{
    const float* X  = (const float*)d_in[0];
    const float* W1 = (const float*)d_in[1];
    const float* b1 = (const float*)d_in[2];
    const float* W2 = (const float*)d_in[3];
    const float* b2 = (const float*)d_in[4];
    const float* Wc = (const float*)d_in[5];
    const float* bc = (const float*)d_in[6];
    const float* Wr = (const float*)d_in[7];
    const float* br = (const float*)d_in[8];
    float* out = (float*)d_out;

    const int M = in_sizes[0] / D_IN;   // 16000

    __nv_bfloat16 *Xhi, *Xlo, *W1hi, *W1lo, *W2hi, *W2lo, *h1hi, *h1lo;
    float* h2;
    cudaGetSymbolAddress((void**)&Xhi, g_Xhi);
    cudaGetSymbolAddress((void**)&Xlo, g_Xlo);
    cudaGetSymbolAddress((void**)&W1hi, g_W1hi);
    cudaGetSymbolAddress((void**)&W1lo, g_W1lo);
    cudaGetSymbolAddress((void**)&W2hi, g_W2hi);
    cudaGetSymbolAddress((void**)&W2lo, g_W2lo);
    cudaGetSymbolAddress((void**)&h1hi, g_h1hi);
    cudaGetSymbolAddress((void**)&h1lo, g_h1lo);
    cudaGetSymbolAddress((void**)&h2, g_h2);

    // conversions
    {
        const size_t n4 = (size_t)M * D_IN / 4;
        split_f32<<<(unsigned)((n4 + 255) / 256), 256>>>(X, Xhi, Xlo, n4);
        dim3 tb(32, 8);
        transpose_split<<<dim3(D_HID / 32, D_IN / 32), tb>>>(W1, W1hi, W1lo, D_IN, D_HID);
        transpose_split<<<dim3(D_HID / 32, D_HID / 32), tb>>>(W2, W2hi, W2lo, D_HID, D_HID);
    }

    cudaFuncSetAttribute(gemm_mma_x3<1>, cudaFuncAttributeMaxDynamicSharedMemorySize, SM_TOTAL);
    cudaFuncSetAttribute(gemm_mma_x3<0>, cudaFuncAttributeMaxDynamicSharedMemorySize, SM_TOTAL);

    dim3 grid(D_HID / 128, M / 128);   // (8, 125) = 1000 CTAs
    gemm_mma_x3<1><<<grid, 512, SM_TOTAL>>>(Xhi, Xlo, W1hi, W1lo, b1, h1hi, h1lo, nullptr, D_IN, D_HID);
    gemm_mma_x3<0><<<grid, 512, SM_TOTAL>>>(h1hi, h1lo, W2hi, W2lo, b2, nullptr, nullptr, h2, D_HID, D_HID);

    const int threads = 256;
    const int blocks = (M * 32 + threads - 1) / threads;
    heads_kernel<<<blocks, threads>>>(h2, Wc, bc, Wr, br, out, M);
}

// round 11
// speedup vs baseline: 1.0180x; 1.0180x over previous
#include <cuda_runtime.h>
#include <cuda_bf16.h>
#include <cstdint>
#include <cstddef>

#define D_IN  12544
#define D_HID 1024
#define MAXN  16000

// ---------------- device scratch (allocation-free rule) ----------------
__device__ __align__(1024) __nv_bfloat16 g_Xhi[(size_t)MAXN * D_IN];
__device__ __align__(1024) __nv_bfloat16 g_Xlo[(size_t)MAXN * D_IN];
__device__ __align__(1024) __nv_bfloat16 g_W1hi[(size_t)D_HID * D_IN];  // [N][K]
__device__ __align__(1024) __nv_bfloat16 g_W1lo[(size_t)D_HID * D_IN];
__device__ __align__(1024) __nv_bfloat16 g_W2hi[(size_t)D_HID * D_HID];
__device__ __align__(1024) __nv_bfloat16 g_W2lo[(size_t)D_HID * D_HID];
__device__ __align__(1024) __nv_bfloat16 g_h1hi[(size_t)MAXN * D_HID];
__device__ __align__(1024) __nv_bfloat16 g_h1lo[(size_t)MAXN * D_HID];
__device__ float g_h2[(size_t)MAXN * D_HID];

// ---------------- asm helpers ----------------
__device__ __forceinline__ uint32_t smem_u32(const void* p) {
    uint32_t a;
    asm("{ .reg .u64 t; cvta.to.shared.u64 t, %1; cvt.u32.u64 %0, t; }" : "=r"(a) : "l"(p));
    return a;
}
__device__ __forceinline__ void cp16(uint32_t dst, const void* src) {
    asm volatile("cp.async.cg.shared.global [%0], [%1], 16;" :: "r"(dst), "l"(src));
}
__device__ __forceinline__ void cp_commit() {
    asm volatile("cp.async.commit_group;" ::: "memory");
}
template <int N>
__device__ __forceinline__ void cp_wait() {
    asm volatile("cp.async.wait_group %0;" :: "n"(N) : "memory");
}
__device__ __forceinline__ void ldm_x4(uint32_t* r, uint32_t addr) {
    asm volatile("ldmatrix.sync.aligned.m8n8.x4.shared.b16 {%0,%1,%2,%3}, [%4];"
                 : "=r"(r[0]), "=r"(r[1]), "=r"(r[2]), "=r"(r[3]) : "r"(addr));
}
__device__ __forceinline__ void mma16816(float* c, const uint32_t* a, uint32_t b0, uint32_t b1) {
    asm volatile(
        "mma.sync.aligned.m16n8k16.row.col.f32.bf16.bf16.f32 "
        "{%0,%1,%2,%3}, {%4,%5,%6,%7}, {%8,%9}, {%0,%1,%2,%3};"
        : "+f"(c[0]), "+f"(c[1]), "+f"(c[2]), "+f"(c[3])
        : "r"(a[0]), "r"(a[1]), "r"(a[2]), "r"(a[3]), "r"(b0), "r"(b1));
}

// ---------------- GEMM: C[M,N] = act(A[M,K] @ B[N,K]^T + bias), bf16 hi/lo x3 ----------------
// CTA tile BM=128, BN=128, BK=32. 4-stage cp.async pipeline, prefetch distance 2.
// Pair-iterations: one barrier + ONE commit (2 stages) per 2 K-iterations, so the
// group drained at each barrier is 2 full iterations old -> drain is nearly free.
// 16 warps (4 M x 4 N), warp tile 32x32, product-major MMA order.
#define LDS       40                    // smem stride in halves (80B) - conflict free
#define TILE_B    (128 * LDS * 2)       // 10240 B per [128][32] bf16 tile
#define OFF_AHI   0
#define OFF_ALO   (TILE_B)
#define OFF_BHI   (2 * TILE_B)
#define OFF_BLO   (3 * TILE_B)
#define STAGE_B   (4 * TILE_B)          // 40960
#define NSTAGE    4
#define SM_TOTAL  (NSTAGE * STAGE_B)    // 163840 -> 1 CTA/SM

__device__ __forceinline__ void load_tile(uint32_t sdst, const __nv_bfloat16* __restrict__ g,
                                          int row0, int K, int k0, int tid)
{
    // 512 threads, 512 x 16B chunks: one chunk per thread
    const char* gb = (const char*)(g + (size_t)row0 * K + k0);
    const int r = tid >> 2;
    const int c = tid & 3;
    cp16(sdst + r * (LDS * 2) + c * 16, gb + (size_t)r * K * 2 + c * 16);
}

__device__ __forceinline__ void load_stage(uint32_t st, const __nv_bfloat16* Ahi,
                                           const __nv_bfloat16* Alo, const __nv_bfloat16* Bhi,
                                           const __nv_bfloat16* Blo, int bm, int bn,
                                           int K, int k0, int tid)
{
    load_tile(st + OFF_AHI, Ahi, bm, K, k0, tid);
    load_tile(st + OFF_ALO, Alo, bm, K, k0, tid);
    load_tile(st + OFF_BHI, Bhi, bn, K, k0, tid);
    load_tile(st + OFF_BLO, Blo, bn, K, k0, tid);
}

template <int WRITE_HILO>
__global__ __launch_bounds__(512, 1)
void gemm_mma_x3(const __nv_bfloat16* __restrict__ Ahi, const __nv_bfloat16* __restrict__ Alo,
                 const __nv_bfloat16* __restrict__ Bhi, const __nv_bfloat16* __restrict__ Blo,
                 const float* __restrict__ bias,
                 __nv_bfloat16* __restrict__ Chi, __nv_bfloat16* __restrict__ Clo,
                 float* __restrict__ Cf,
                 int K, int N)
{
    extern __shared__ char smem[];
    const uint32_t sb = smem_u32(smem);
    const int tid  = threadIdx.x;
    const int wid  = tid >> 5;
    const int lane = tid & 31;
    const int wm   = wid & 3;        // 0..3 (M)
    const int wn   = wid >> 2;       // 0..3 (N)

    const int bm = blockIdx.y * 128;
    const int bn = blockIdx.x * 128;
    const int NK = K / 32;           // even for both GEMMs (392, 32)

    float acc[2][4][4];
#pragma unroll
    for (int mt = 0; mt < 2; mt++)
#pragma unroll
        for (int nb = 0; nb < 4; nb++)
#pragma unroll
            for (int q = 0; q < 4; q++) acc[mt][nb][q] = 0.0f;

    // prologue: prefetch stages 0, 1 as ONE group
    load_stage(sb + 0 * STAGE_B, Ahi, Alo, Bhi, Blo, bm, bn, K, 0, tid);
    load_stage(sb + 1 * STAGE_B, Ahi, Alo, Bhi, Blo, bm, bn, K, 32, tid);
    cp_commit();

    // ldmatrix lane addressing (within-tile offsets, in bytes)
    const uint32_t a_lane_off = ((lane & 15) * LDS + (lane >> 4) * 8) * 2;
    const uint32_t b_lane_off = ((((lane >> 4) * 8) + (lane & 7)) * LDS + (((lane >> 3) & 1) * 8)) * 2;
    const uint32_t a_base_off = (wm * 32) * (LDS * 2);
    const uint32_t b_base_off = (wn * 32) * (LDS * 2);

    for (int c2 = 0; c2 < NK; c2 += 2) {
        // the only outstanding group was committed 2 iterations ago -> cheap drain
        cp_wait<0>();
        __syncthreads();

        // prefetch stages c2+2, c2+3 as ONE group
        if (c2 + 2 < NK) {
            load_stage(sb + ((c2 + 2) & 3) * STAGE_B, Ahi, Alo, Bhi, Blo, bm, bn, K, (c2 + 2) * 32, tid);
            if (c2 + 3 < NK)
                load_stage(sb + ((c2 + 3) & 3) * STAGE_B, Ahi, Alo, Bhi, Blo, bm, bn, K, (c2 + 3) * 32, tid);
        }
        cp_commit();

        // consume stages c2, c2+1 (4 kk-steps)
#pragma unroll
        for (int half_it = 0; half_it < 2; half_it++) {
            const uint32_t st = sb + ((c2 + half_it) & 3) * STAGE_B;
            const uint32_t sAh = st + OFF_AHI + a_base_off + a_lane_off;
            const uint32_t sAl = st + OFF_ALO + a_base_off + a_lane_off;
            const uint32_t sBh = st + OFF_BHI + b_base_off + b_lane_off;
            const uint32_t sBl = st + OFF_BLO + b_base_off + b_lane_off;

#pragma unroll
            for (int kk = 0; kk < 2; kk++) {
                const uint32_t ko = kk * 16 * 2;
                uint32_t ah[2][4], al[2][4];
#pragma unroll
                for (int mt = 0; mt < 2; mt++) {
                    ldm_x4(ah[mt], sAh + mt * 16 * (LDS * 2) + ko);
                    ldm_x4(al[mt], sAl + mt * 16 * (LDS * 2) + ko);
                }
                uint32_t bh[2][4], bl[2][4];
#pragma unroll
                for (int pi = 0; pi < 2; pi++) {
                    ldm_x4(bh[pi], sBh + pi * 16 * (LDS * 2) + ko);
                    ldm_x4(bl[pi], sBl + pi * 16 * (LDS * 2) + ko);
                }
                // product-major: 8 independent MMAs per product
#pragma unroll
                for (int mt = 0; mt < 2; mt++)
#pragma unroll
                    for (int pi = 0; pi < 2; pi++)
#pragma unroll
                        for (int h = 0; h < 2; h++)
                            mma16816(acc[mt][pi * 2 + h], ah[mt], bh[pi][h * 2], bh[pi][h * 2 + 1]);
#pragma unroll
                for (int mt = 0; mt < 2; mt++)
#pragma unroll
                    for (int pi = 0; pi < 2; pi++)
#pragma unroll
                        for (int h = 0; h < 2; h++)
                            mma16816(acc[mt][pi * 2 + h], ah[mt], bl[pi][h * 2], bl[pi][h * 2 + 1]);
#pragma unroll
                for (int mt = 0; mt < 2; mt++)
#pragma unroll
                    for (int pi = 0; pi < 2; pi++)
#pragma unroll
                        for (int h = 0; h < 2; h++)
                            mma16816(acc[mt][pi * 2 + h], al[mt], bh[pi][h * 2], bh[pi][h * 2 + 1]);
            }
        }
    }

    // ---------------- epilogue: bias + ReLU ----------------
#pragma unroll
    for (int mt = 0; mt < 2; mt++) {
        const int row0 = bm + wm * 32 + mt * 16 + (lane >> 2);
#pragma unroll
        for (int nb = 0; nb < 4; nb++) {
            const int col = bn + wn * 32 + nb * 8 + (lane & 3) * 2;
            const float bx = bias[col];
            const float by = bias[col + 1];
            float y0 = fmaxf(acc[mt][nb][0] + bx, 0.0f);
            float y1 = fmaxf(acc[mt][nb][1] + by, 0.0f);
            float y2 = fmaxf(acc[mt][nb][2] + bx, 0.0f);
            float y3 = fmaxf(acc[mt][nb][3] + by, 0.0f);
            if (WRITE_HILO) {
                __nv_bfloat16 h0 = __float2bfloat16(y0), h1 = __float2bfloat16(y1);
                __nv_bfloat16 h2 = __float2bfloat16(y2), h3 = __float2bfloat16(y3);
                __nv_bfloat16 l0 = __float2bfloat16(y0 - __bfloat162float(h0));
                __nv_bfloat16 l1 = __float2bfloat16(y1 - __bfloat162float(h1));
                __nv_bfloat16 l2 = __float2bfloat16(y2 - __bfloat162float(h2));
                __nv_bfloat16 l3 = __float2bfloat16(y3 - __bfloat162float(h3));
                *(__nv_bfloat162*)(Chi + (size_t)row0 * N + col)       = __nv_bfloat162(h0, h1);
                *(__nv_bfloat162*)(Chi + (size_t)(row0 + 8) * N + col) = __nv_bfloat162(h2, h3);
                *(__nv_bfloat162*)(Clo + (size_t)row0 * N + col)       = __nv_bfloat162(l0, l1);
                *(__nv_bfloat162*)(Clo + (size_t)(row0 + 8) * N + col) = __nv_bfloat162(l2, l3);
            } else {
                *(float2*)(Cf + (size_t)row0 * N + col)       = make_float2(y0, y1);
                *(float2*)(Cf + (size_t)(row0 + 8) * N + col) = make_float2(y2, y3);
            }
        }
    }
}

// ---------------- conversion kernels ----------------
__global__ __launch_bounds__(256)
void split_f32(const float* __restrict__ in, __nv_bfloat16* __restrict__ hi,
               __nv_bfloat16* __restrict__ lo, size_t n4)
{
    size_t i = (size_t)blockIdx.x * blockDim.x + threadIdx.x;
    if (i >= n4) return;
    float4 v = ((const float4*)in)[i];
    __nv_bfloat16 h0 = __float2bfloat16(v.x), h1 = __float2bfloat16(v.y);
    __nv_bfloat16 h2 = __float2bfloat16(v.z), h3 = __float2bfloat16(v.w);
    __nv_bfloat16 l0 = __float2bfloat16(v.x - __bfloat162float(h0));
    __nv_bfloat16 l1 = __float2bfloat16(v.y - __bfloat162float(h1));
    __nv_bfloat16 l2 = __float2bfloat16(v.z - __bfloat162float(h2));
    __nv_bfloat16 l3 = __float2bfloat16(v.w - __bfloat162float(h3));
    ((__nv_bfloat162*)hi)[i * 2 + 0] = __nv_bfloat162(h0, h1);
    ((__nv_bfloat162*)hi)[i * 2 + 1] = __nv_bfloat162(h2, h3);
    ((__nv_bfloat162*)lo)[i * 2 + 0] = __nv_bfloat162(l0, l1);
    ((__nv_bfloat162*)lo)[i * 2 + 1] = __nv_bfloat162(l2, l3);
}

// in: [K][N] fp32 row-major -> out hi/lo: [N][K] bf16 row-major
__global__ __launch_bounds__(256)
void transpose_split(const float* __restrict__ in, __nv_bfloat16* __restrict__ hi,
                     __nv_bfloat16* __restrict__ lo, int K, int N)
{
    __shared__ float t[32][33];
    const int k0 = blockIdx.y * 32;
    const int n0 = blockIdx.x * 32;
    const int tx = threadIdx.x;
    const int ty = threadIdx.y;
#pragma unroll
    for (int r = 0; r < 4; r++) {
        const int k = k0 + ty * 4 + r;
        t[ty * 4 + r][tx] = in[(size_t)k * N + n0 + tx];
    }
    __syncthreads();
#pragma unroll
    for (int r = 0; r < 4; r++) {
        const int n = n0 + ty * 4 + r;
        const float v = t[tx][ty * 4 + r];
        const __nv_bfloat16 h = __float2bfloat16(v);
        const __nv_bfloat16 l = __float2bfloat16(v - __bfloat162float(h));
        hi[(size_t)n * K + k0 + tx] = h;
        lo[(size_t)n * K + k0 + tx] = l;
    }
}

// ---------------- heads ----------------
__global__ __launch_bounds__(256)
void heads_kernel(const float* __restrict__ H,
                  const float* __restrict__ Wc, const float* __restrict__ bc,
                  const float* __restrict__ Wr, const float* __restrict__ br,
                  float* __restrict__ out, int M)
{
    const int warp = (blockIdx.x * blockDim.x + threadIdx.x) >> 5;
    const int lane = threadIdx.x & 31;
    if (warp >= M) return;

    const float* __restrict__ h = H + (size_t)warp * D_HID;
    float acc[16];
#pragma unroll
    for (int c = 0; c < 16; c++) acc[c] = 0.0f;

    for (int k = lane; k < D_HID; k += 32) {
        const float x = h[k];
        const float* wc = Wc + (size_t)k * 4;
#pragma unroll
        for (int c = 0; c < 4; c++) acc[c] = fmaf(x, wc[c], acc[c]);
        const float* wr = Wr + (size_t)k * 12;
#pragma unroll
        for (int c = 0; c < 12; c++) acc[4 + c] = fmaf(x, wr[c], acc[4 + c]);
    }
#pragma unroll
    for (int c = 0; c < 16; c++)
#pragma unroll
        for (int off = 16; off > 0; off >>= 1)
            acc[c] += __shfl_xor_sync(0xffffffffu, acc[c], off);

    if (lane < 4) {
        out[(size_t)warp * 4 + lane] = acc[lane] + bc[lane];
    } else if (lane < 16) {
        out[(size_t)M * 4 + (size_t)warp * 12 + (lane - 4)] = acc[lane] + br[lane - 4];
    }
}

// ---------------- host ----------------
extern "C" void kernel_launch(void* const* d_in, const int* in_sizes, int n_in,
                              void* d_out, int out_size)
{
    const float* X  = (const float*)d_in[0];
    const float* W1 = (const float*)d_in[1];
    const float* b1 = (const float*)d_in[2];
    const float* W2 = (const float*)d_in[3];
    const float* b2 = (const float*)d_in[4];
    const float* Wc = (const float*)d_in[5];
    const float* bc = (const float*)d_in[6];
    const float* Wr = (const float*)d_in[7];
    const float* br = (const float*)d_in[8];
    float* out = (float*)d_out;

    const int M = in_sizes[0] / D_IN;   // 16000

    __nv_bfloat16 *Xhi, *Xlo, *W1hi, *W1lo, *W2hi, *W2lo, *h1hi, *h1lo;
    float* h2;
    cudaGetSymbolAddress((void**)&Xhi, g_Xhi);
    cudaGetSymbolAddress((void**)&Xlo, g_Xlo);
    cudaGetSymbolAddress((void**)&W1hi, g_W1hi);
    cudaGetSymbolAddress((void**)&W1lo, g_W1lo);
    cudaGetSymbolAddress((void**)&W2hi, g_W2hi);
    cudaGetSymbolAddress((void**)&W2lo, g_W2lo);
    cudaGetSymbolAddress((void**)&h1hi, g_h1hi);
    cudaGetSymbolAddress((void**)&h1lo, g_h1lo);
    cudaGetSymbolAddress((void**)&h2, g_h2);

    // conversions
    {
        const size_t n4 = (size_t)M * D_IN / 4;
        split_f32<<<(unsigned)((n4 + 255) / 256), 256>>>(X, Xhi, Xlo, n4);
        dim3 tb(32, 8);
        transpose_split<<<dim3(D_HID / 32, D_IN / 32), tb>>>(W1, W1hi, W1lo, D_IN, D_HID);
        transpose_split<<<dim3(D_HID / 32, D_HID / 32), tb>>>(W2, W2hi, W2lo, D_HID, D_HID);
    }

    cudaFuncSetAttribute(gemm_mma_x3<1>, cudaFuncAttributeMaxDynamicSharedMemorySize, SM_TOTAL);
    cudaFuncSetAttribute(gemm_mma_x3<0>, cudaFuncAttributeMaxDynamicSharedMemorySize, SM_TOTAL);

    dim3 grid(D_HID / 128, M / 128);   // (8, 125) = 1000 CTAs
    gemm_mma_x3<1><<<grid, 512, SM_TOTAL>>>(Xhi, Xlo, W1hi, W1lo, b1, h1hi, h1lo, nullptr, D_IN, D_HID);
    gemm_mma_x3<0><<<grid, 512, SM_TOTAL>>>(h1hi, h1lo, W2hi, W2lo, b2, nullptr, nullptr, h2, D_HID, D_HID);

    const int threads = 256;
    const int blocks = (M * 32 + threads - 1) / threads;
    heads_kernel<<<blocks, threads>>>(h2, Wc, bc, Wr, br, out, M);
}

// round 12
// speedup vs baseline: 1.0666x; 1.0477x over previous
#include <cuda_runtime.h>
#include <cuda_bf16.h>
#include <cstdint>
#include <cstddef>

#define D_IN  12544
#define D_HID 1024
#define MAXN  16000

// ---------------- device scratch (allocation-free rule) ----------------
__device__ __align__(1024) __nv_bfloat16 g_W1hi[(size_t)D_HID * D_IN];  // [N][K]
__device__ __align__(1024) __nv_bfloat16 g_W1lo[(size_t)D_HID * D_IN];
__device__ __align__(1024) __nv_bfloat16 g_W2hi[(size_t)D_HID * D_HID];
__device__ __align__(1024) __nv_bfloat16 g_W2lo[(size_t)D_HID * D_HID];
__device__ __align__(1024) float g_h1[(size_t)MAXN * D_HID];
__device__ __align__(1024) float g_h2[(size_t)MAXN * D_HID];

// ---------------- asm helpers ----------------
__device__ __forceinline__ uint32_t smem_u32(const void* p) {
    uint32_t a;
    asm("{ .reg .u64 t; cvta.to.shared.u64 t, %1; cvt.u32.u64 %0, t; }" : "=r"(a) : "l"(p));
    return a;
}
__device__ __forceinline__ void cp16(uint32_t dst, const void* src) {
    asm volatile("cp.async.cg.shared.global [%0], [%1], 16;" :: "r"(dst), "l"(src));
}
__device__ __forceinline__ void cp_commit() {
    asm volatile("cp.async.commit_group;" ::: "memory");
}
template <int N>
__device__ __forceinline__ void cp_wait() {
    asm volatile("cp.async.wait_group %0;" :: "n"(N) : "memory");
}
__device__ __forceinline__ void ldm_x4(uint32_t* r, uint32_t addr) {
    asm volatile("ldmatrix.sync.aligned.m8n8.x4.shared.b16 {%0,%1,%2,%3}, [%4];"
                 : "=r"(r[0]), "=r"(r[1]), "=r"(r[2]), "=r"(r[3]) : "r"(addr));
}
__device__ __forceinline__ float2 lds64(uint32_t addr) {
    float2 f;
    asm volatile("ld.shared.v2.f32 {%0,%1}, [%2];" : "=f"(f.x), "=f"(f.y) : "r"(addr));
    return f;
}
__device__ __forceinline__ void mma16816(float* c, const uint32_t* a, uint32_t b0, uint32_t b1) {
    asm volatile(
        "mma.sync.aligned.m16n8k16.row.col.f32.bf16.bf16.f32 "
        "{%0,%1,%2,%3}, {%4,%5,%6,%7}, {%8,%9}, {%0,%1,%2,%3};"
        : "+f"(c[0]), "+f"(c[1]), "+f"(c[2]), "+f"(c[3])
        : "r"(a[0]), "r"(a[1]), "r"(a[2]), "r"(a[3]), "r"(b0), "r"(b1));
}

// split a float2 into packed bf16x2 hi and lo (lo = residual), mma reg layout
__device__ __forceinline__ void cvt_split(float2 f, uint32_t& hi, uint32_t& lo) {
    __nv_bfloat162 h2 = __float22bfloat162_rn(f);  // .x -> low half
    hi = *reinterpret_cast<uint32_t*>(&h2);
    const float h0 = __uint_as_float(hi << 16);
    const float h1 = __uint_as_float(hi & 0xffff0000u);
    float2 r;
    r.x = f.x - h0;
    r.y = f.y - h1;
    __nv_bfloat162 l2 = __float22bfloat162_rn(r);
    lo = *reinterpret_cast<uint32_t*>(&l2);
}

// ---------------- GEMM: C[M,N] = relu(A[M,K] @ B[N,K]^T + bias), fp32 A split in-kernel ----------------
// CTA tile BM=128, BN=128, BK=32. R9 pipeline: 4 stages, prefetch distance 2,
// barrier every 2 iterations. 16 warps (4 M x 4 N), warp tile 32x32, product-major MMAs.
// A arrives fp32 via cp.async (same bytes as bf16 hi+lo); hi/lo split happens in registers.
#define LDSB_A    160                   // fp32 A tile row stride bytes (128+32): conflict-free LDS.64
#define LDS       40                    // bf16 B tile stride in halves (80B)
#define TILE_XB   (128 * LDSB_A)        // 20480 B fp32 A tile [128][32]
#define TILE_B    (128 * LDS * 2)       // 10240 B bf16 tile [128][32]
#define OFF_X     0
#define OFF_BHI   (TILE_XB)
#define OFF_BLO   (TILE_XB + TILE_B)
#define STAGE_B   (TILE_XB + 2 * TILE_B)  // 40960
#define NSTAGE    4
#define SM_TOTAL  (NSTAGE * STAGE_B)      // 163840 -> 1 CTA/SM

__device__ __forceinline__ void load_tileX(uint32_t sdst, const float* __restrict__ g,
                                           int row0, int K, int k0, int tid)
{
    // 128 rows x 8 chunks(16B) = 1024 chunks; 512 threads -> 2 each
    const char* gb = (const char*)(g + (size_t)row0 * K + k0);
    const int r = tid >> 2;
#pragma unroll
    for (int p = 0; p < 2; p++) {
        const int c = (tid & 3) + p * 4;
        cp16(sdst + r * LDSB_A + c * 16, gb + (size_t)r * K * 4 + c * 16);
    }
}
__device__ __forceinline__ void load_tileB(uint32_t sdst, const __nv_bfloat16* __restrict__ g,
                                           int row0, int K, int k0, int tid)
{
    const char* gb = (const char*)(g + (size_t)row0 * K + k0);
    const int r = tid >> 2;
    const int c = tid & 3;
    cp16(sdst + r * (LDS * 2) + c * 16, gb + (size_t)r * K * 2 + c * 16);
}

__global__ __launch_bounds__(512, 1)
void gemm_fused_split(const float* __restrict__ A,
                      const __nv_bfloat16* __restrict__ Bhi, const __nv_bfloat16* __restrict__ Blo,
                      const float* __restrict__ bias,
                      float* __restrict__ C,
                      int K, int N)
{
    extern __shared__ char smem[];
    const uint32_t sb = smem_u32(smem);
    const int tid  = threadIdx.x;
    const int wid  = tid >> 5;
    const int lane = tid & 31;
    const int wm   = wid & 3;        // 0..3 (M)
    const int wn   = wid >> 2;       // 0..3 (N)

    const int bm = blockIdx.y * 128;
    const int bn = blockIdx.x * 128;
    const int NK = K / 32;           // even (392, 32)

    float acc[2][4][4];
#pragma unroll
    for (int mt = 0; mt < 2; mt++)
#pragma unroll
        for (int nb = 0; nb < 4; nb++)
#pragma unroll
            for (int q = 0; q < 4; q++) acc[mt][nb][q] = 0.0f;

    // prologue: prefetch stages 0, 1 (R9 structure: one commit per stage)
#pragma unroll
    for (int s = 0; s < 2; s++) {
        const uint32_t st = sb + s * STAGE_B;
        load_tileX(st + OFF_X,   A,   bm, K, s * 32, tid);
        load_tileB(st + OFF_BHI, Bhi, bn, K, s * 32, tid);
        load_tileB(st + OFF_BLO, Blo, bn, K, s * 32, tid);
        cp_commit();
    }

    // A fragment lane addressing (fp32 tile, bytes):
    //   row = wm*32 + mt*16 + (lane>>2) (+8), col floats = kk*16 + (lane&3)*2 (+8)
    const uint32_t a_lane = (uint32_t)(wm * 32 + (lane >> 2)) * LDSB_A + (uint32_t)(lane & 3) * 8;
    // B ldmatrix lane addressing (bf16 tile, bytes)
    const uint32_t b_lane_off = ((((lane >> 4) * 8) + (lane & 7)) * LDS + (((lane >> 3) & 1) * 8)) * 2;
    const uint32_t b_base_off = (wn * 32) * (LDS * 2);

    for (int c = 0; c < NK; c++) {
        if ((c & 1) == 0) {
            cp_wait<0>();
            __syncthreads();
        }

        // prefetch stage c+2
        const int pf = c + 2;
        if (pf < NK) {
            const uint32_t st = sb + (pf & 3) * STAGE_B;
            load_tileX(st + OFF_X,   A,   bm, K, pf * 32, tid);
            load_tileB(st + OFF_BHI, Bhi, bn, K, pf * 32, tid);
            load_tileB(st + OFF_BLO, Blo, bn, K, pf * 32, tid);
        }
        cp_commit();

        const uint32_t st = sb + (c & 3) * STAGE_B;
        const uint32_t sX  = st + OFF_X + a_lane;
        const uint32_t sBh = st + OFF_BHI + b_base_off + b_lane_off;
        const uint32_t sBl = st + OFF_BLO + b_base_off + b_lane_off;

#pragma unroll
        for (int kk = 0; kk < 2; kk++) {
            const uint32_t koA = kk * 64;       // 16 floats
            const uint32_t koB = kk * 16 * 2;   // 16 halves

            // ---- A fragments: fp32 load + in-register bf16 hi/lo split ----
            uint32_t ah[2][4], al[2][4];
#pragma unroll
            for (int mt = 0; mt < 2; mt++) {
                const uint32_t rb = sX + (uint32_t)(mt * 16) * LDSB_A + koA;
                // j: 0->(r,k) 1->(r+8,k) 2->(r,k+8) 3->(r+8,k+8)
                cvt_split(lds64(rb),                       ah[mt][0], al[mt][0]);
                cvt_split(lds64(rb + 8 * LDSB_A),          ah[mt][1], al[mt][1]);
                cvt_split(lds64(rb + 32),                  ah[mt][2], al[mt][2]);
                cvt_split(lds64(rb + 8 * LDSB_A + 32),     ah[mt][3], al[mt][3]);
            }
            // ---- B fragments via ldmatrix ----
            uint32_t bh[2][4], bl[2][4];
#pragma unroll
            for (int pi = 0; pi < 2; pi++) {
                ldm_x4(bh[pi], sBh + pi * 16 * (LDS * 2) + koB);
                ldm_x4(bl[pi], sBl + pi * 16 * (LDS * 2) + koB);
            }
            // product-major: 8 independent MMAs per product
#pragma unroll
            for (int mt = 0; mt < 2; mt++)
#pragma unroll
                for (int pi = 0; pi < 2; pi++)
#pragma unroll
                    for (int h = 0; h < 2; h++)
                        mma16816(acc[mt][pi * 2 + h], ah[mt], bh[pi][h * 2], bh[pi][h * 2 + 1]);
#pragma unroll
            for (int mt = 0; mt < 2; mt++)
#pragma unroll
                for (int pi = 0; pi < 2; pi++)
#pragma unroll
                    for (int h = 0; h < 2; h++)
                        mma16816(acc[mt][pi * 2 + h], ah[mt], bl[pi][h * 2], bl[pi][h * 2 + 1]);
#pragma unroll
            for (int mt = 0; mt < 2; mt++)
#pragma unroll
                for (int pi = 0; pi < 2; pi++)
#pragma unroll
                    for (int h = 0; h < 2; h++)
                        mma16816(acc[mt][pi * 2 + h], al[mt], bh[pi][h * 2], bh[pi][h * 2 + 1]);
        }
    }

    // ---------------- epilogue: bias + ReLU, fp32 out ----------------
#pragma unroll
    for (int mt = 0; mt < 2; mt++) {
        const int row0 = bm + wm * 32 + mt * 16 + (lane >> 2);
#pragma unroll
        for (int nb = 0; nb < 4; nb++) {
            const int col = bn + wn * 32 + nb * 8 + (lane & 3) * 2;
            const float bx = bias[col];
            const float by = bias[col + 1];
            float2 v0, v1;
            v0.x = fmaxf(acc[mt][nb][0] + bx, 0.0f);
            v0.y = fmaxf(acc[mt][nb][1] + by, 0.0f);
            v1.x = fmaxf(acc[mt][nb][2] + bx, 0.0f);
            v1.y = fmaxf(acc[mt][nb][3] + by, 0.0f);
            *(float2*)(C + (size_t)row0 * N + col)       = v0;
            *(float2*)(C + (size_t)(row0 + 8) * N + col) = v1;
        }
    }
}

// ---------------- weight transpose+split: [K][N] fp32 -> [N][K] bf16 hi/lo ----------------
__global__ __launch_bounds__(256)
void transpose_split(const float* __restrict__ in, __nv_bfloat16* __restrict__ hi,
                     __nv_bfloat16* __restrict__ lo, int K, int N)
{
    __shared__ float t[32][33];
    const int k0 = blockIdx.y * 32;
    const int n0 = blockIdx.x * 32;
    const int tx = threadIdx.x;
    const int ty = threadIdx.y;
#pragma unroll
    for (int r = 0; r < 4; r++) {
        const int k = k0 + ty * 4 + r;
        t[ty * 4 + r][tx] = in[(size_t)k * N + n0 + tx];
    }
    __syncthreads();
#pragma unroll
    for (int r = 0; r < 4; r++) {
        const int n = n0 + ty * 4 + r;
        const float v = t[tx][ty * 4 + r];
        const __nv_bfloat16 h = __float2bfloat16(v);
        const __nv_bfloat16 l = __float2bfloat16(v - __bfloat162float(h));
        hi[(size_t)n * K + k0 + tx] = h;
        lo[(size_t)n * K + k0 + tx] = l;
    }
}

// ---------------- heads ----------------
__global__ __launch_bounds__(256)
void heads_kernel(const float* __restrict__ H,
                  const float* __restrict__ Wc, const float* __restrict__ bc,
                  const float* __restrict__ Wr, const float* __restrict__ br,
                  float* __restrict__ out, int M)
{
    const int warp = (blockIdx.x * blockDim.x + threadIdx.x) >> 5;
    const int lane = threadIdx.x & 31;
    if (warp >= M) return;

    const float* __restrict__ h = H + (size_t)warp * D_HID;
    float acc[16];
#pragma unroll
    for (int c = 0; c < 16; c++) acc[c] = 0.0f;

    for (int k = lane; k < D_HID; k += 32) {
        const float x = h[k];
        const float* wc = Wc + (size_t)k * 4;
#pragma unroll
        for (int c = 0; c < 4; c++) acc[c] = fmaf(x, wc[c], acc[c]);
        const float* wr = Wr + (size_t)k * 12;
#pragma unroll
        for (int c = 0; c < 12; c++) acc[4 + c] = fmaf(x, wr[c], acc[4 + c]);
    }
#pragma unroll
    for (int c = 0; c < 16; c++)
#pragma unroll
        for (int off = 16; off > 0; off >>= 1)
            acc[c] += __shfl_xor_sync(0xffffffffu, acc[c], off);

    if (lane < 4) {
        out[(size_t)warp * 4 + lane] = acc[lane] + bc[lane];
    } else if (lane < 16) {
        out[(size_t)M * 4 + (size_t)warp * 12 + (lane - 4)] = acc[lane] + br[lane - 4];
    }
}

// ---------------- host ----------------
extern "C" void kernel_launch(void* const* d_in, const int* in_sizes, int n_in,
                              void* d_out, int out_size)
{
    const float* X  = (const float*)d_in[0];
    const float* W1 = (const float*)d_in[1];
    const float* b1 = (const float*)d_in[2];
    const float* W2 = (const float*)d_in[3];
    const float* b2 = (const float*)d_in[4];
    const float* Wc = (const float*)d_in[5];
    const float* bc = (const float*)d_in[6];
    const float* Wr = (const float*)d_in[7];
    const float* br = (const float*)d_in[8];
    float* out = (float*)d_out;

    const int M = in_sizes[0] / D_IN;   // 16000

    __nv_bfloat16 *W1hi, *W1lo, *W2hi, *W2lo;
    float *h1, *h2;
    cudaGetSymbolAddress((void**)&W1hi, g_W1hi);
    cudaGetSymbolAddress((void**)&W1lo, g_W1lo);
    cudaGetSymbolAddress((void**)&W2hi, g_W2hi);
    cudaGetSymbolAddress((void**)&W2lo, g_W2lo);
    cudaGetSymbolAddress((void**)&h1, g_h1);
    cudaGetSymbolAddress((void**)&h2, g_h2);

    // weight conversions (cheap: 55 MB total)
    {
        dim3 tb(32, 8);
        transpose_split<<<dim3(D_HID / 32, D_IN / 32), tb>>>(W1, W1hi, W1lo, D_IN, D_HID);
        transpose_split<<<dim3(D_HID / 32, D_HID / 32), tb>>>(W2, W2hi, W2lo, D_HID, D_HID);
    }

    cudaFuncSetAttribute(gemm_fused_split, cudaFuncAttributeMaxDynamicSharedMemorySize, SM_TOTAL);

    dim3 grid(D_HID / 128, M / 128);   // (8, 125) = 1000 CTAs
    gemm_fused_split<<<grid, 512, SM_TOTAL>>>(X,  W1hi, W1lo, b1, h1, D_IN,  D_HID);
    gemm_fused_split<<<grid, 512, SM_TOTAL>>>(h1, W2hi, W2lo, b2, h2, D_HID, D_HID);

    const int threads = 256;
    const int blocks = (M * 32 + threads - 1) / threads;
    heads_kernel<<<blocks, threads>>>(h2, Wc, bc, Wr, br, out, M);
}

// round 13
// speedup vs baseline: 1.5435x; 1.4472x over previous
#include <cuda_runtime.h>
#include <cuda_bf16.h>
#include <cuda_fp16.h>
#include <cstdint>
#include <cstddef>

#define D_IN  12544
#define D_HID 1024
#define MAXN  16000

// ---------------- device scratch (allocation-free rule) ----------------
__device__ __align__(1024) __half g_Xhi[(size_t)MAXN * D_IN];
__device__ __align__(1024) __half g_Xlo[(size_t)MAXN * D_IN];
__device__ __align__(1024) __half g_W1[(size_t)D_HID * D_IN];           // [N][K] fp16 single
__device__ __align__(1024) __nv_bfloat16 g_W2hi[(size_t)D_HID * D_HID]; // [N][K]
__device__ __align__(1024) __nv_bfloat16 g_W2lo[(size_t)D_HID * D_HID];
__device__ __align__(1024) __nv_bfloat16 g_h1hi[(size_t)MAXN * D_HID];
__device__ __align__(1024) __nv_bfloat16 g_h1lo[(size_t)MAXN * D_HID];
__device__ float g_h2[(size_t)MAXN * D_HID];

// ---------------- asm helpers ----------------
__device__ __forceinline__ uint32_t smem_u32(const void* p) {
    uint32_t a;
    asm("{ .reg .u64 t; cvta.to.shared.u64 t, %1; cvt.u32.u64 %0, t; }" : "=r"(a) : "l"(p));
    return a;
}
__device__ __forceinline__ void cp16(uint32_t dst, const void* src) {
    asm volatile("cp.async.cg.shared.global [%0], [%1], 16;" :: "r"(dst), "l"(src));
}
__device__ __forceinline__ void cp_commit() {
    asm volatile("cp.async.commit_group;" ::: "memory");
}
template <int N>
__device__ __forceinline__ void cp_wait() {
    asm volatile("cp.async.wait_group %0;" :: "n"(N) : "memory");
}
__device__ __forceinline__ void ldm_x4(uint32_t* r, uint32_t addr) {
    asm volatile("ldmatrix.sync.aligned.m8n8.x4.shared.b16 {%0,%1,%2,%3}, [%4];"
                 : "=r"(r[0]), "=r"(r[1]), "=r"(r[2]), "=r"(r[3]) : "r"(addr));
}
__device__ __forceinline__ void mma_bf16(float* c, const uint32_t* a, uint32_t b0, uint32_t b1) {
    asm volatile(
        "mma.sync.aligned.m16n8k16.row.col.f32.bf16.bf16.f32 "
        "{%0,%1,%2,%3}, {%4,%5,%6,%7}, {%8,%9}, {%0,%1,%2,%3};"
        : "+f"(c[0]), "+f"(c[1]), "+f"(c[2]), "+f"(c[3])
        : "r"(a[0]), "r"(a[1]), "r"(a[2]), "r"(a[3]), "r"(b0), "r"(b1));
}
__device__ __forceinline__ void mma_f16(float* c, const uint32_t* a, uint32_t b0, uint32_t b1) {
    asm volatile(
        "mma.sync.aligned.m16n8k16.row.col.f32.f16.f16.f32 "
        "{%0,%1,%2,%3}, {%4,%5,%6,%7}, {%8,%9}, {%0,%1,%2,%3};"
        : "+f"(c[0]), "+f"(c[1]), "+f"(c[2]), "+f"(c[3])
        : "r"(a[0]), "r"(a[1]), "r"(a[2]), "r"(a[3]), "r"(b0), "r"(b1));
}

// ---------------- common tile geometry (R9) ----------------
#define LDS       40                    // smem stride in halves (80B) - conflict free
#define TILE_B    (128 * LDS * 2)       // 10240 B per [128][32] 16-bit tile

__device__ __forceinline__ void load_tile16(uint32_t sdst, const void* __restrict__ g,
                                            int row0, int K, int k0, int tid)
{
    // 512 threads, 512 x 16B chunks: one chunk per thread (2-byte elems)
    const char* gb = (const char*)g + ((size_t)row0 * K + k0) * 2;
    const int r = tid >> 2;
    const int c = tid & 3;
    cp16(sdst + r * (LDS * 2) + c * 16, gb + (size_t)r * K * 2 + c * 16);
}

// ============================================================================
// GEMM1: h1 = relu(X @ W1^T + b1); X = fp16 hi+lo (exact), W1 = fp16 single.
// 2 products/iter (16 MMAs). R9 pipeline: 4 stages, prefetch dist 2, barrier/2 iters.
// Epilogue writes h1 as bf16 hi/lo for GEMM2.
// ============================================================================
#define OFF1_AHI  0
#define OFF1_ALO  (TILE_B)
#define OFF1_B    (2 * TILE_B)
#define STAGE1_B  (3 * TILE_B)          // 30720
#define SM1_TOTAL (4 * STAGE1_B)        // 122880 -> 1 CTA/SM

__global__ __launch_bounds__(512, 1)
void gemm1_f16x2(const __half* __restrict__ Ahi, const __half* __restrict__ Alo,
                 const __half* __restrict__ B,
                 const float* __restrict__ bias,
                 __nv_bfloat16* __restrict__ Chi, __nv_bfloat16* __restrict__ Clo,
                 int K, int N)
{
    extern __shared__ char smem[];
    const uint32_t sb = smem_u32(smem);
    const int tid  = threadIdx.x;
    const int wid  = tid >> 5;
    const int lane = tid & 31;
    const int wm   = wid & 3;
    const int wn   = wid >> 2;

    const int bm = blockIdx.y * 128;
    const int bn = blockIdx.x * 128;
    const int NK = K / 32;               // 392, even

    float acc[2][4][4];
#pragma unroll
    for (int mt = 0; mt < 2; mt++)
#pragma unroll
        for (int nb = 0; nb < 4; nb++)
#pragma unroll
            for (int q = 0; q < 4; q++) acc[mt][nb][q] = 0.0f;

#pragma unroll
    for (int s = 0; s < 2; s++) {
        const uint32_t st = sb + s * STAGE1_B;
        load_tile16(st + OFF1_AHI, Ahi, bm, K, s * 32, tid);
        load_tile16(st + OFF1_ALO, Alo, bm, K, s * 32, tid);
        load_tile16(st + OFF1_B,   B,   bn, K, s * 32, tid);
        cp_commit();
    }

    const uint32_t a_lane_off = ((lane & 15) * LDS + (lane >> 4) * 8) * 2;
    const uint32_t b_lane_off = ((((lane >> 4) * 8) + (lane & 7)) * LDS + (((lane >> 3) & 1) * 8)) * 2;
    const uint32_t a_base_off = (wm * 32) * (LDS * 2);
    const uint32_t b_base_off = (wn * 32) * (LDS * 2);

    for (int c = 0; c < NK; c++) {
        if ((c & 1) == 0) {
            cp_wait<0>();
            __syncthreads();
        }

        const int pf = c + 2;
        if (pf < NK) {
            const uint32_t st = sb + (pf & 3) * STAGE1_B;
            load_tile16(st + OFF1_AHI, Ahi, bm, K, pf * 32, tid);
            load_tile16(st + OFF1_ALO, Alo, bm, K, pf * 32, tid);
            load_tile16(st + OFF1_B,   B,   bn, K, pf * 32, tid);
        }
        cp_commit();

        const uint32_t st = sb + (c & 3) * STAGE1_B;
        const uint32_t sAh = st + OFF1_AHI + a_base_off + a_lane_off;
        const uint32_t sAl = st + OFF1_ALO + a_base_off + a_lane_off;
        const uint32_t sB  = st + OFF1_B   + b_base_off + b_lane_off;

#pragma unroll
        for (int kk = 0; kk < 2; kk++) {
            const uint32_t ko = kk * 16 * 2;
            uint32_t ah[2][4], al[2][4];
#pragma unroll
            for (int mt = 0; mt < 2; mt++) {
                ldm_x4(ah[mt], sAh + mt * 16 * (LDS * 2) + ko);
                ldm_x4(al[mt], sAl + mt * 16 * (LDS * 2) + ko);
            }
            uint32_t bf[2][4];
#pragma unroll
            for (int pi = 0; pi < 2; pi++)
                ldm_x4(bf[pi], sB + pi * 16 * (LDS * 2) + ko);

            // product 1: Ahi * B (8 independent MMAs)
#pragma unroll
            for (int mt = 0; mt < 2; mt++)
#pragma unroll
                for (int pi = 0; pi < 2; pi++)
#pragma unroll
                    for (int h = 0; h < 2; h++)
                        mma_f16(acc[mt][pi * 2 + h], ah[mt], bf[pi][h * 2], bf[pi][h * 2 + 1]);
            // product 2: Alo * B
#pragma unroll
            for (int mt = 0; mt < 2; mt++)
#pragma unroll
                for (int pi = 0; pi < 2; pi++)
#pragma unroll
                    for (int h = 0; h < 2; h++)
                        mma_f16(acc[mt][pi * 2 + h], al[mt], bf[pi][h * 2], bf[pi][h * 2 + 1]);
        }
    }

    // epilogue: bias + ReLU -> bf16 hi/lo
#pragma unroll
    for (int mt = 0; mt < 2; mt++) {
        const int row0 = bm + wm * 32 + mt * 16 + (lane >> 2);
#pragma unroll
        for (int nb = 0; nb < 4; nb++) {
            const int col = bn + wn * 32 + nb * 8 + (lane & 3) * 2;
            const float bx = bias[col];
            const float by = bias[col + 1];
            float y0 = fmaxf(acc[mt][nb][0] + bx, 0.0f);
            float y1 = fmaxf(acc[mt][nb][1] + by, 0.0f);
            float y2 = fmaxf(acc[mt][nb][2] + bx, 0.0f);
            float y3 = fmaxf(acc[mt][nb][3] + by, 0.0f);
            __nv_bfloat16 h0 = __float2bfloat16(y0), h1 = __float2bfloat16(y1);
            __nv_bfloat16 h2 = __float2bfloat16(y2), h3 = __float2bfloat16(y3);
            __nv_bfloat16 l0 = __float2bfloat16(y0 - __bfloat162float(h0));
            __nv_bfloat16 l1 = __float2bfloat16(y1 - __bfloat162float(h1));
            __nv_bfloat16 l2 = __float2bfloat16(y2 - __bfloat162float(h2));
            __nv_bfloat16 l3 = __float2bfloat16(y3 - __bfloat162float(h3));
            *(__nv_bfloat162*)(Chi + (size_t)row0 * N + col)       = __nv_bfloat162(h0, h1);
            *(__nv_bfloat162*)(Chi + (size_t)(row0 + 8) * N + col) = __nv_bfloat162(h2, h3);
            *(__nv_bfloat162*)(Clo + (size_t)row0 * N + col)       = __nv_bfloat162(l0, l1);
            *(__nv_bfloat162*)(Clo + (size_t)(row0 + 8) * N + col) = __nv_bfloat162(l2, l3);
        }
    }
}

// ============================================================================
// GEMM2: h2 = relu(h1 @ W2^T + b2), bf16 hi/lo x3 (R9 kernel, fp32 out)
// ============================================================================
#define OFF_AHI   0
#define OFF_ALO   (TILE_B)
#define OFF_BHI   (2 * TILE_B)
#define OFF_BLO   (3 * TILE_B)
#define STAGE_B   (4 * TILE_B)          // 40960
#define SM2_TOTAL (4 * STAGE_B)         // 163840 -> 1 CTA/SM

__global__ __launch_bounds__(512, 1)
void gemm2_bf16x3(const __nv_bfloat16* __restrict__ Ahi, const __nv_bfloat16* __restrict__ Alo,
                  const __nv_bfloat16* __restrict__ Bhi, const __nv_bfloat16* __restrict__ Blo,
                  const float* __restrict__ bias,
                  float* __restrict__ Cf,
                  int K, int N)
{
    extern __shared__ char smem[];
    const uint32_t sb = smem_u32(smem);
    const int tid  = threadIdx.x;
    const int wid  = tid >> 5;
    const int lane = tid & 31;
    const int wm   = wid & 3;
    const int wn   = wid >> 2;

    const int bm = blockIdx.y * 128;
    const int bn = blockIdx.x * 128;
    const int NK = K / 32;               // 32, even

    float acc[2][4][4];
#pragma unroll
    for (int mt = 0; mt < 2; mt++)
#pragma unroll
        for (int nb = 0; nb < 4; nb++)
#pragma unroll
            for (int q = 0; q < 4; q++) acc[mt][nb][q] = 0.0f;

#pragma unroll
    for (int s = 0; s < 2; s++) {
        const uint32_t st = sb + s * STAGE_B;
        load_tile16(st + OFF_AHI, Ahi, bm, K, s * 32, tid);
        load_tile16(st + OFF_ALO, Alo, bm, K, s * 32, tid);
        load_tile16(st + OFF_BHI, Bhi, bn, K, s * 32, tid);
        load_tile16(st + OFF_BLO, Blo, bn, K, s * 32, tid);
        cp_commit();
    }

    const uint32_t a_lane_off = ((lane & 15) * LDS + (lane >> 4) * 8) * 2;
    const uint32_t b_lane_off = ((((lane >> 4) * 8) + (lane & 7)) * LDS + (((lane >> 3) & 1) * 8)) * 2;
    const uint32_t a_base_off = (wm * 32) * (LDS * 2);
    const uint32_t b_base_off = (wn * 32) * (LDS * 2);

    for (int c = 0; c < NK; c++) {
        if ((c & 1) == 0) {
            cp_wait<0>();
            __syncthreads();
        }

        const int pf = c + 2;
        if (pf < NK) {
            const uint32_t st = sb + (pf & 3) * STAGE_B;
            load_tile16(st + OFF_AHI, Ahi, bm, K, pf * 32, tid);
            load_tile16(st + OFF_ALO, Alo, bm, K, pf * 32, tid);
            load_tile16(st + OFF_BHI, Bhi, bn, K, pf * 32, tid);
            load_tile16(st + OFF_BLO, Blo, bn, K, pf * 32, tid);
        }
        cp_commit();

        const uint32_t st = sb + (c & 3) * STAGE_B;
        const uint32_t sAh = st + OFF_AHI + a_base_off + a_lane_off;
        const uint32_t sAl = st + OFF_ALO + a_base_off + a_lane_off;
        const uint32_t sBh = st + OFF_BHI + b_base_off + b_lane_off;
        const uint32_t sBl = st + OFF_BLO + b_base_off + b_lane_off;

#pragma unroll
        for (int kk = 0; kk < 2; kk++) {
            const uint32_t ko = kk * 16 * 2;
            uint32_t ah[2][4], al[2][4];
#pragma unroll
            for (int mt = 0; mt < 2; mt++) {
                ldm_x4(ah[mt], sAh + mt * 16 * (LDS * 2) + ko);
                ldm_x4(al[mt], sAl + mt * 16 * (LDS * 2) + ko);
            }
            uint32_t bh[2][4], bl[2][4];
#pragma unroll
            for (int pi = 0; pi < 2; pi++) {
                ldm_x4(bh[pi], sBh + pi * 16 * (LDS * 2) + ko);
                ldm_x4(bl[pi], sBl + pi * 16 * (LDS * 2) + ko);
            }
#pragma unroll
            for (int mt = 0; mt < 2; mt++)
#pragma unroll
                for (int pi = 0; pi < 2; pi++)
#pragma unroll
                    for (int h = 0; h < 2; h++)
                        mma_bf16(acc[mt][pi * 2 + h], ah[mt], bh[pi][h * 2], bh[pi][h * 2 + 1]);
#pragma unroll
            for (int mt = 0; mt < 2; mt++)
#pragma unroll
                for (int pi = 0; pi < 2; pi++)
#pragma unroll
                    for (int h = 0; h < 2; h++)
                        mma_bf16(acc[mt][pi * 2 + h], ah[mt], bl[pi][h * 2], bl[pi][h * 2 + 1]);
#pragma unroll
            for (int mt = 0; mt < 2; mt++)
#pragma unroll
                for (int pi = 0; pi < 2; pi++)
#pragma unroll
                    for (int h = 0; h < 2; h++)
                        mma_bf16(acc[mt][pi * 2 + h], al[mt], bh[pi][h * 2], bh[pi][h * 2 + 1]);
        }
    }

#pragma unroll
    for (int mt = 0; mt < 2; mt++) {
        const int row0 = bm + wm * 32 + mt * 16 + (lane >> 2);
#pragma unroll
        for (int nb = 0; nb < 4; nb++) {
            const int col = bn + wn * 32 + nb * 8 + (lane & 3) * 2;
            const float bx = bias[col];
            const float by = bias[col + 1];
            float2 v0, v1;
            v0.x = fmaxf(acc[mt][nb][0] + bx, 0.0f);
            v0.y = fmaxf(acc[mt][nb][1] + by, 0.0f);
            v1.x = fmaxf(acc[mt][nb][2] + bx, 0.0f);
            v1.y = fmaxf(acc[mt][nb][3] + by, 0.0f);
            *(float2*)(Cf + (size_t)row0 * N + col)       = v0;
            *(float2*)(Cf + (size_t)(row0 + 8) * N + col) = v1;
        }
    }
}

// ---------------- conversion kernels ----------------
// X fp32 -> fp16 hi + fp16 lo (exact two-term split)
__global__ __launch_bounds__(256)
void split_x_f16(const float* __restrict__ in, __half* __restrict__ hi,
                 __half* __restrict__ lo, size_t n4)
{
    size_t i = (size_t)blockIdx.x * blockDim.x + threadIdx.x;
    if (i >= n4) return;
    float4 v = ((const float4*)in)[i];
    __half h0 = __float2half_rn(v.x), h1 = __float2half_rn(v.y);
    __half h2 = __float2half_rn(v.z), h3 = __float2half_rn(v.w);
    __half l0 = __float2half_rn(v.x - __half2float(h0));
    __half l1 = __float2half_rn(v.y - __half2float(h1));
    __half l2 = __float2half_rn(v.z - __half2float(h2));
    __half l3 = __float2half_rn(v.w - __half2float(h3));
    ((__half2*)hi)[i * 2 + 0] = __half2(h0, h1);
    ((__half2*)hi)[i * 2 + 1] = __half2(h2, h3);
    ((__half2*)lo)[i * 2 + 0] = __half2(l0, l1);
    ((__half2*)lo)[i * 2 + 1] = __half2(l2, l3);
}

// W1: [K][N] fp32 -> [N][K] fp16 single
__global__ __launch_bounds__(256)
void transpose_f16(const float* __restrict__ in, __half* __restrict__ out, int K, int N)
{
    __shared__ float t[32][33];
    const int k0 = blockIdx.y * 32;
    const int n0 = blockIdx.x * 32;
    const int tx = threadIdx.x;
    const int ty = threadIdx.y;
#pragma unroll
    for (int r = 0; r < 4; r++) {
        const int k = k0 + ty * 4 + r;
        t[ty * 4 + r][tx] = in[(size_t)k * N + n0 + tx];
    }
    __syncthreads();
#pragma unroll
    for (int r = 0; r < 4; r++) {
        const int n = n0 + ty * 4 + r;
        out[(size_t)n * K + k0 + tx] = __float2half_rn(t[tx][ty * 4 + r]);
    }
}

// W2: [K][N] fp32 -> [N][K] bf16 hi/lo
__global__ __launch_bounds__(256)
void transpose_split(const float* __restrict__ in, __nv_bfloat16* __restrict__ hi,
                     __nv_bfloat16* __restrict__ lo, int K, int N)
{
    __shared__ float t[32][33];
    const int k0 = blockIdx.y * 32;
    const int n0 = blockIdx.x * 32;
    const int tx = threadIdx.x;
    const int ty = threadIdx.y;
#pragma unroll
    for (int r = 0; r < 4; r++) {
        const int k = k0 + ty * 4 + r;
        t[ty * 4 + r][tx] = in[(size_t)k * N + n0 + tx];
    }
    __syncthreads();
#pragma unroll
    for (int r = 0; r < 4; r++) {
        const int n = n0 + ty * 4 + r;
        const float v = t[tx][ty * 4 + r];
        const __nv_bfloat16 h = __float2bfloat16(v);
        const __nv_bfloat16 l = __float2bfloat16(v - __bfloat162float(h));
        hi[(size_t)n * K + k0 + tx] = h;
        lo[(size_t)n * K + k0 + tx] = l;
    }
}

// ---------------- heads ----------------
__global__ __launch_bounds__(256)
void heads_kernel(const float* __restrict__ H,
                  const float* __restrict__ Wc, const float* __restrict__ bc,
                  const float* __restrict__ Wr, const float* __restrict__ br,
                  float* __restrict__ out, int M)
{
    const int warp = (blockIdx.x * blockDim.x + threadIdx.x) >> 5;
    const int lane = threadIdx.x & 31;
    if (warp >= M) return;

    const float* __restrict__ h = H + (size_t)warp * D_HID;
    float acc[16];
#pragma unroll
    for (int c = 0; c < 16; c++) acc[c] = 0.0f;

    for (int k = lane; k < D_HID; k += 32) {
        const float x = h[k];
        const float* wc = Wc + (size_t)k * 4;
#pragma unroll
        for (int c = 0; c < 4; c++) acc[c] = fmaf(x, wc[c], acc[c]);
        const float* wr = Wr + (size_t)k * 12;
#pragma unroll
        for (int c = 0; c < 12; c++) acc[4 + c] = fmaf(x, wr[c], acc[4 + c]);
    }
#pragma unroll
    for (int c = 0; c < 16; c++)
#pragma unroll
        for (int off = 16; off > 0; off >>= 1)
            acc[c] += __shfl_xor_sync(0xffffffffu, acc[c], off);

    if (lane < 4) {
        out[(size_t)warp * 4 + lane] = acc[lane] + bc[lane];
    } else if (lane < 16) {
        out[(size_t)M * 4 + (size_t)warp * 12 + (lane - 4)] = acc[lane] + br[lane - 4];
    }
}

// ---------------- host ----------------
extern "C" void kernel_launch(void* const* d_in, const int* in_sizes, int n_in,
                              void* d_out, int out_size)
{
    const float* X  = (const float*)d_in[0];
    const float* W1 = (const float*)d_in[1];
    const float* b1 = (const float*)d_in[2];
    const float* W2 = (const float*)d_in[3];
    const float* b2 = (const float*)d_in[4];
    const float* Wc = (const float*)d_in[5];
    const float* bc = (const float*)d_in[6];
    const float* Wr = (const float*)d_in[7];
    const float* br = (const float*)d_in[8];
    float* out = (float*)d_out;

    const int M = in_sizes[0] / D_IN;   // 16000

    __half *Xhi, *Xlo, *W1h;
    __nv_bfloat16 *W2hi, *W2lo, *h1hi, *h1lo;
    float* h2;
    cudaGetSymbolAddress((void**)&Xhi, g_Xhi);
    cudaGetSymbolAddress((void**)&Xlo, g_Xlo);
    cudaGetSymbolAddress((void**)&W1h, g_W1);
    cudaGetSymbolAddress((void**)&W2hi, g_W2hi);
    cudaGetSymbolAddress((void**)&W2lo, g_W2lo);
    cudaGetSymbolAddress((void**)&h1hi, g_h1hi);
    cudaGetSymbolAddress((void**)&h1lo, g_h1lo);
    cudaGetSymbolAddress((void**)&h2, g_h2);

    // conversions
    {
        const size_t n4 = (size_t)M * D_IN / 4;
        split_x_f16<<<(unsigned)((n4 + 255) / 256), 256>>>(X, Xhi, Xlo, n4);
        dim3 tb(32, 8);
        transpose_f16<<<dim3(D_HID / 32, D_IN / 32), tb>>>(W1, W1h, D_IN, D_HID);
        transpose_split<<<dim3(D_HID / 32, D_HID / 32), tb>>>(W2, W2hi, W2lo, D_HID, D_HID);
    }

    cudaFuncSetAttribute(gemm1_f16x2, cudaFuncAttributeMaxDynamicSharedMemorySize, SM1_TOTAL);
    cudaFuncSetAttribute(gemm2_bf16x3, cudaFuncAttributeMaxDynamicSharedMemorySize, SM2_TOTAL);

    dim3 grid(D_HID / 128, M / 128);   // (8, 125) = 1000 CTAs
    gemm1_f16x2<<<grid, 512, SM1_TOTAL>>>(Xhi, Xlo, W1h, b1, h1hi, h1lo, D_IN, D_HID);
    gemm2_bf16x3<<<grid, 512, SM2_TOTAL>>>(h1hi, h1lo, W2hi, W2lo, b2, h2, D_HID, D_HID);

    const int threads = 256;
    const int blocks = (M * 32 + threads - 1) / threads;
    heads_kernel<<<blocks, threads>>>(h2, Wc, bc, Wr, br, out, M);
}

// round 14
// speedup vs baseline: 2.2021x; 1.4267x over previous
#include <cuda_runtime.h>
#include <cuda_bf16.h>
#include <cuda_fp16.h>
#include <cstdint>
#include <cstddef>

#define D_IN  12544
#define D_HID 1024
#define MAXN  16000

// ---------------- device scratch (allocation-free rule) ----------------
__device__ __align__(1024) __half g_X16[(size_t)MAXN * D_IN];
__device__ __align__(1024) __half g_W1[(size_t)D_HID * D_IN];           // [N][K] fp16 single
__device__ __align__(1024) __nv_bfloat16 g_W2hi[(size_t)D_HID * D_HID]; // [N][K]
__device__ __align__(1024) __nv_bfloat16 g_W2lo[(size_t)D_HID * D_HID];
__device__ __align__(1024) __nv_bfloat16 g_h1hi[(size_t)MAXN * D_HID];
__device__ __align__(1024) __nv_bfloat16 g_h1lo[(size_t)MAXN * D_HID];
__device__ float g_h2[(size_t)MAXN * D_HID];

// ---------------- asm helpers ----------------
__device__ __forceinline__ uint32_t smem_u32(const void* p) {
    uint32_t a;
    asm("{ .reg .u64 t; cvta.to.shared.u64 t, %1; cvt.u32.u64 %0, t; }" : "=r"(a) : "l"(p));
    return a;
}
__device__ __forceinline__ void cp16(uint32_t dst, const void* src) {
    asm volatile("cp.async.cg.shared.global [%0], [%1], 16;" :: "r"(dst), "l"(src));
}
__device__ __forceinline__ void cp_commit() {
    asm volatile("cp.async.commit_group;" ::: "memory");
}
template <int N>
__device__ __forceinline__ void cp_wait() {
    asm volatile("cp.async.wait_group %0;" :: "n"(N) : "memory");
}
__device__ __forceinline__ void ldm_x4(uint32_t* r, uint32_t addr) {
    asm volatile("ldmatrix.sync.aligned.m8n8.x4.shared.b16 {%0,%1,%2,%3}, [%4];"
                 : "=r"(r[0]), "=r"(r[1]), "=r"(r[2]), "=r"(r[3]) : "r"(addr));
}
__device__ __forceinline__ void mma_bf16(float* c, const uint32_t* a, uint32_t b0, uint32_t b1) {
    asm volatile(
        "mma.sync.aligned.m16n8k16.row.col.f32.bf16.bf16.f32 "
        "{%0,%1,%2,%3}, {%4,%5,%6,%7}, {%8,%9}, {%0,%1,%2,%3};"
        : "+f"(c[0]), "+f"(c[1]), "+f"(c[2]), "+f"(c[3])
        : "r"(a[0]), "r"(a[1]), "r"(a[2]), "r"(a[3]), "r"(b0), "r"(b1));
}
__device__ __forceinline__ void mma_f16(float* c, const uint32_t* a, uint32_t b0, uint32_t b1) {
    asm volatile(
        "mma.sync.aligned.m16n8k16.row.col.f32.f16.f16.f32 "
        "{%0,%1,%2,%3}, {%4,%5,%6,%7}, {%8,%9}, {%0,%1,%2,%3};"
        : "+f"(c[0]), "+f"(c[1]), "+f"(c[2]), "+f"(c[3])
        : "r"(a[0]), "r"(a[1]), "r"(a[2]), "r"(a[3]), "r"(b0), "r"(b1));
}

// ---------------- common tile geometry (R9) ----------------
#define LDS       40                    // smem stride in halves (80B) - conflict free
#define TILE_B    (128 * LDS * 2)       // 10240 B per [128][32] 16-bit tile

__device__ __forceinline__ void load_tile16(uint32_t sdst, const void* __restrict__ g,
                                            int row0, int K, int k0, int tid)
{
    // 512 threads, 512 x 16B chunks: one chunk per thread (2-byte elems)
    const char* gb = (const char*)g + ((size_t)row0 * K + k0) * 2;
    const int r = tid >> 2;
    const int c = tid & 3;
    cp16(sdst + r * (LDS * 2) + c * 16, gb + (size_t)r * K * 2 + c * 16);
}

// ============================================================================
// GEMM1: h1 = relu(X @ W1^T + b1); X, W1 = single fp16 -> 1 product (8 MMAs/kk).
// R9 pipeline: 4 stages, prefetch dist 2, barrier every 2 iters.
// 16 warps (4 M x 4 N), warp tile 32x32. Epilogue writes h1 as bf16 hi/lo.
// ============================================================================
#define OFF1_A    0
#define OFF1_B    (TILE_B)
#define STAGE1_B  (2 * TILE_B)          // 20480
#define SM1_TOTAL (4 * STAGE1_B)        // 81920

__global__ __launch_bounds__(512, 1)
void gemm1_f16(const __half* __restrict__ A, const __half* __restrict__ B,
               const float* __restrict__ bias,
               __nv_bfloat16* __restrict__ Chi, __nv_bfloat16* __restrict__ Clo,
               int K, int N)
{
    extern __shared__ char smem[];
    const uint32_t sb = smem_u32(smem);
    const int tid  = threadIdx.x;
    const int wid  = tid >> 5;
    const int lane = tid & 31;
    const int wm   = wid & 3;
    const int wn   = wid >> 2;

    const int bm = blockIdx.y * 128;
    const int bn = blockIdx.x * 128;
    const int NK = K / 32;               // 392, even

    float acc[2][4][4];
#pragma unroll
    for (int mt = 0; mt < 2; mt++)
#pragma unroll
        for (int nb = 0; nb < 4; nb++)
#pragma unroll
            for (int q = 0; q < 4; q++) acc[mt][nb][q] = 0.0f;

#pragma unroll
    for (int s = 0; s < 2; s++) {
        const uint32_t st = sb + s * STAGE1_B;
        load_tile16(st + OFF1_A, A, bm, K, s * 32, tid);
        load_tile16(st + OFF1_B, B, bn, K, s * 32, tid);
        cp_commit();
    }

    const uint32_t a_lane_off = ((lane & 15) * LDS + (lane >> 4) * 8) * 2;
    const uint32_t b_lane_off = ((((lane >> 4) * 8) + (lane & 7)) * LDS + (((lane >> 3) & 1) * 8)) * 2;
    const uint32_t a_base_off = (wm * 32) * (LDS * 2);
    const uint32_t b_base_off = (wn * 32) * (LDS * 2);

    for (int c = 0; c < NK; c++) {
        if ((c & 1) == 0) {
            cp_wait<0>();
            __syncthreads();
        }

        const int pf = c + 2;
        if (pf < NK) {
            const uint32_t st = sb + (pf & 3) * STAGE1_B;
            load_tile16(st + OFF1_A, A, bm, K, pf * 32, tid);
            load_tile16(st + OFF1_B, B, bn, K, pf * 32, tid);
        }
        cp_commit();

        const uint32_t st = sb + (c & 3) * STAGE1_B;
        const uint32_t sA = st + OFF1_A + a_base_off + a_lane_off;
        const uint32_t sB = st + OFF1_B + b_base_off + b_lane_off;

#pragma unroll
        for (int kk = 0; kk < 2; kk++) {
            const uint32_t ko = kk * 16 * 2;
            uint32_t af[2][4];
#pragma unroll
            for (int mt = 0; mt < 2; mt++)
                ldm_x4(af[mt], sA + mt * 16 * (LDS * 2) + ko);
            uint32_t bf[2][4];
#pragma unroll
            for (int pi = 0; pi < 2; pi++)
                ldm_x4(bf[pi], sB + pi * 16 * (LDS * 2) + ko);

#pragma unroll
            for (int mt = 0; mt < 2; mt++)
#pragma unroll
                for (int pi = 0; pi < 2; pi++)
#pragma unroll
                    for (int h = 0; h < 2; h++)
                        mma_f16(acc[mt][pi * 2 + h], af[mt], bf[pi][h * 2], bf[pi][h * 2 + 1]);
        }
    }

    // epilogue: bias + ReLU -> bf16 hi/lo
#pragma unroll
    for (int mt = 0; mt < 2; mt++) {
        const int row0 = bm + wm * 32 + mt * 16 + (lane >> 2);
#pragma unroll
        for (int nb = 0; nb < 4; nb++) {
            const int col = bn + wn * 32 + nb * 8 + (lane & 3) * 2;
            const float bx = bias[col];
            const float by = bias[col + 1];
            float y0 = fmaxf(acc[mt][nb][0] + bx, 0.0f);
            float y1 = fmaxf(acc[mt][nb][1] + by, 0.0f);
            float y2 = fmaxf(acc[mt][nb][2] + bx, 0.0f);
            float y3 = fmaxf(acc[mt][nb][3] + by, 0.0f);
            __nv_bfloat16 h0 = __float2bfloat16(y0), h1 = __float2bfloat16(y1);
            __nv_bfloat16 h2 = __float2bfloat16(y2), h3 = __float2bfloat16(y3);
            __nv_bfloat16 l0 = __float2bfloat16(y0 - __bfloat162float(h0));
            __nv_bfloat16 l1 = __float2bfloat16(y1 - __bfloat162float(h1));
            __nv_bfloat16 l2 = __float2bfloat16(y2 - __bfloat162float(h2));
            __nv_bfloat16 l3 = __float2bfloat16(y3 - __bfloat162float(h3));
            *(__nv_bfloat162*)(Chi + (size_t)row0 * N + col)       = __nv_bfloat162(h0, h1);
            *(__nv_bfloat162*)(Chi + (size_t)(row0 + 8) * N + col) = __nv_bfloat162(h2, h3);
            *(__nv_bfloat162*)(Clo + (size_t)row0 * N + col)       = __nv_bfloat162(l0, l1);
            *(__nv_bfloat162*)(Clo + (size_t)(row0 + 8) * N + col) = __nv_bfloat162(l2, l3);
        }
    }
}

// ============================================================================
// GEMM2: h2 = relu(h1 @ W2^T + b2), bf16 hi/lo x3 (R9 kernel, fp32 out)
// ============================================================================
#define OFF_AHI   0
#define OFF_ALO   (TILE_B)
#define OFF_BHI   (2 * TILE_B)
#define OFF_BLO   (3 * TILE_B)
#define STAGE_B   (4 * TILE_B)          // 40960
#define SM2_TOTAL (4 * STAGE_B)         // 163840

__global__ __launch_bounds__(512, 1)
void gemm2_bf16x3(const __nv_bfloat16* __restrict__ Ahi, const __nv_bfloat16* __restrict__ Alo,
                  const __nv_bfloat16* __restrict__ Bhi, const __nv_bfloat16* __restrict__ Blo,
                  const float* __restrict__ bias,
                  float* __restrict__ Cf,
                  int K, int N)
{
    extern __shared__ char smem[];
    const uint32_t sb = smem_u32(smem);
    const int tid  = threadIdx.x;
    const int wid  = tid >> 5;
    const int lane = tid & 31;
    const int wm   = wid & 3;
    const int wn   = wid >> 2;

    const int bm = blockIdx.y * 128;
    const int bn = blockIdx.x * 128;
    const int NK = K / 32;               // 32, even

    float acc[2][4][4];
#pragma unroll
    for (int mt = 0; mt < 2; mt++)
#pragma unroll
        for (int nb = 0; nb < 4; nb++)
#pragma unroll
            for (int q = 0; q < 4; q++) acc[mt][nb][q] = 0.0f;

#pragma unroll
    for (int s = 0; s < 2; s++) {
        const uint32_t st = sb + s * STAGE_B;
        load_tile16(st + OFF_AHI, Ahi, bm, K, s * 32, tid);
        load_tile16(st + OFF_ALO, Alo, bm, K, s * 32, tid);
        load_tile16(st + OFF_BHI, Bhi, bn, K, s * 32, tid);
        load_tile16(st + OFF_BLO, Blo, bn, K, s * 32, tid);
        cp_commit();
    }

    const uint32_t a_lane_off = ((lane & 15) * LDS + (lane >> 4) * 8) * 2;
    const uint32_t b_lane_off = ((((lane >> 4) * 8) + (lane & 7)) * LDS + (((lane >> 3) & 1) * 8)) * 2;
    const uint32_t a_base_off = (wm * 32) * (LDS * 2);
    const uint32_t b_base_off = (wn * 32) * (LDS * 2);

    for (int c = 0; c < NK; c++) {
        if ((c & 1) == 0) {
            cp_wait<0>();
            __syncthreads();
        }

        const int pf = c + 2;
        if (pf < NK) {
            const uint32_t st = sb + (pf & 3) * STAGE_B;
            load_tile16(st + OFF_AHI, Ahi, bm, K, pf * 32, tid);
            load_tile16(st + OFF_ALO, Alo, bm, K, pf * 32, tid);
            load_tile16(st + OFF_BHI, Bhi, bn, K, pf * 32, tid);
            load_tile16(st + OFF_BLO, Blo, bn, K, pf * 32, tid);
        }
        cp_commit();

        const uint32_t st = sb + (c & 3) * STAGE_B;
        const uint32_t sAh = st + OFF_AHI + a_base_off + a_lane_off;
        const uint32_t sAl = st + OFF_ALO + a_base_off + a_lane_off;
        const uint32_t sBh = st + OFF_BHI + b_base_off + b_lane_off;
        const uint32_t sBl = st + OFF_BLO + b_base_off + b_lane_off;

#pragma unroll
        for (int kk = 0; kk < 2; kk++) {
            const uint32_t ko = kk * 16 * 2;
            uint32_t ah[2][4], al[2][4];
#pragma unroll
            for (int mt = 0; mt < 2; mt++) {
                ldm_x4(ah[mt], sAh + mt * 16 * (LDS * 2) + ko);
                ldm_x4(al[mt], sAl + mt * 16 * (LDS * 2) + ko);
            }
            uint32_t bh[2][4], bl[2][4];
#pragma unroll
            for (int pi = 0; pi < 2; pi++) {
                ldm_x4(bh[pi], sBh + pi * 16 * (LDS * 2) + ko);
                ldm_x4(bl[pi], sBl + pi * 16 * (LDS * 2) + ko);
            }
#pragma unroll
            for (int mt = 0; mt < 2; mt++)
#pragma unroll
                for (int pi = 0; pi < 2; pi++)
#pragma unroll
                    for (int h = 0; h < 2; h++)
                        mma_bf16(acc[mt][pi * 2 + h], ah[mt], bh[pi][h * 2], bh[pi][h * 2 + 1]);
#pragma unroll
            for (int mt = 0; mt < 2; mt++)
#pragma unroll
                for (int pi = 0; pi < 2; pi++)
#pragma unroll
                    for (int h = 0; h < 2; h++)
                        mma_bf16(acc[mt][pi * 2 + h], ah[mt], bl[pi][h * 2], bl[pi][h * 2 + 1]);
#pragma unroll
            for (int mt = 0; mt < 2; mt++)
#pragma unroll
                for (int pi = 0; pi < 2; pi++)
#pragma unroll
                    for (int h = 0; h < 2; h++)
                        mma_bf16(acc[mt][pi * 2 + h], al[mt], bh[pi][h * 2], bh[pi][h * 2 + 1]);
        }
    }

#pragma unroll
    for (int mt = 0; mt < 2; mt++) {
        const int row0 = bm + wm * 32 + mt * 16 + (lane >> 2);
#pragma unroll
        for (int nb = 0; nb < 4; nb++) {
            const int col = bn + wn * 32 + nb * 8 + (lane & 3) * 2;
            const float bx = bias[col];
            const float by = bias[col + 1];
            float2 v0, v1;
            v0.x = fmaxf(acc[mt][nb][0] + bx, 0.0f);
            v0.y = fmaxf(acc[mt][nb][1] + by, 0.0f);
            v1.x = fmaxf(acc[mt][nb][2] + bx, 0.0f);
            v1.y = fmaxf(acc[mt][nb][3] + by, 0.0f);
            *(float2*)(Cf + (size_t)row0 * N + col)       = v0;
            *(float2*)(Cf + (size_t)(row0 + 8) * N + col) = v1;
        }
    }
}

// ---------------- conversion kernels ----------------
// X fp32 -> fp16 single
__global__ __launch_bounds__(256)
void conv_x_f16(const float* __restrict__ in, __half* __restrict__ out, size_t n4)
{
    size_t i = (size_t)blockIdx.x * blockDim.x + threadIdx.x;
    if (i >= n4) return;
    float4 v = ((const float4*)in)[i];
    ((__half2*)out)[i * 2 + 0] = __half2(__float2half_rn(v.x), __float2half_rn(v.y));
    ((__half2*)out)[i * 2 + 1] = __half2(__float2half_rn(v.z), __float2half_rn(v.w));
}

// W1: [K][N] fp32 -> [N][K] fp16 single
__global__ __launch_bounds__(256)
void transpose_f16(const float* __restrict__ in, __half* __restrict__ out, int K, int N)
{
    __shared__ float t[32][33];
    const int k0 = blockIdx.y * 32;
    const int n0 = blockIdx.x * 32;
    const int tx = threadIdx.x;
    const int ty = threadIdx.y;
#pragma unroll
    for (int r = 0; r < 4; r++) {
        const int k = k0 + ty * 4 + r;
        t[ty * 4 + r][tx] = in[(size_t)k * N + n0 + tx];
    }
    __syncthreads();
#pragma unroll
    for (int r = 0; r < 4; r++) {
        const int n = n0 + ty * 4 + r;
        out[(size_t)n * K + k0 + tx] = __float2half_rn(t[tx][ty * 4 + r]);
    }
}

// W2: [K][N] fp32 -> [N][K] bf16 hi/lo
__global__ __launch_bounds__(256)
void transpose_split(const float* __restrict__ in, __nv_bfloat16* __restrict__ hi,
                     __nv_bfloat16* __restrict__ lo, int K, int N)
{
    __shared__ float t[32][33];
    const int k0 = blockIdx.y * 32;
    const int n0 = blockIdx.x * 32;
    const int tx = threadIdx.x;
    const int ty = threadIdx.y;
#pragma unroll
    for (int r = 0; r < 4; r++) {
        const int k = k0 + ty * 4 + r;
        t[ty * 4 + r][tx] = in[(size_t)k * N + n0 + tx];
    }
    __syncthreads();
#pragma unroll
    for (int r = 0; r < 4; r++) {
        const int n = n0 + ty * 4 + r;
        const float v = t[tx][ty * 4 + r];
        const __nv_bfloat16 h = __float2bfloat16(v);
        const __nv_bfloat16 l = __float2bfloat16(v - __bfloat162float(h));
        hi[(size_t)n * K + k0 + tx] = h;
        lo[(size_t)n * K + k0 + tx] = l;
    }
}

// ---------------- heads ----------------
__global__ __launch_bounds__(256)
void heads_kernel(const float* __restrict__ H,
                  const float* __restrict__ Wc, const float* __restrict__ bc,
                  const float* __restrict__ Wr, const float* __restrict__ br,
                  float* __restrict__ out, int M)
{
    const int warp = (blockIdx.x * blockDim.x + threadIdx.x) >> 5;
    const int lane = threadIdx.x & 31;
    if (warp >= M) return;

    const float* __restrict__ h = H + (size_t)warp * D_HID;
    float acc[16];
#pragma unroll
    for (int c = 0; c < 16; c++) acc[c] = 0.0f;

    for (int k = lane; k < D_HID; k += 32) {
        const float x = h[k];
        const float* wc = Wc + (size_t)k * 4;
#pragma unroll
        for (int c = 0; c < 4; c++) acc[c] = fmaf(x, wc[c], acc[c]);
        const float* wr = Wr + (size_t)k * 12;
#pragma unroll
        for (int c = 0; c < 12; c++) acc[4 + c] = fmaf(x, wr[c], acc[4 + c]);
    }
#pragma unroll
    for (int c = 0; c < 16; c++)
#pragma unroll
        for (int off = 16; off > 0; off >>= 1)
            acc[c] += __shfl_xor_sync(0xffffffffu, acc[c], off);

    if (lane < 4) {
        out[(size_t)warp * 4 + lane] = acc[lane] + bc[lane];
    } else if (lane < 16) {
        out[(size_t)M * 4 + (size_t)warp * 12 + (lane - 4)] = acc[lane] + br[lane - 4];
    }
}

// ---------------- host ----------------
extern "C" void kernel_launch(void* const* d_in, const int* in_sizes, int n_in,
                              void* d_out, int out_size)
{
    const float* X  = (const float*)d_in[0];
    const float* W1 = (const float*)d_in[1];
    const float* b1 = (const float*)d_in[2];
    const float* W2 = (const float*)d_in[3];
    const float* b2 = (const float*)d_in[4];
    const float* Wc = (const float*)d_in[5];
    const float* bc = (const float*)d_in[6];
    const float* Wr = (const float*)d_in[7];
    const float* br = (const float*)d_in[8];
    float* out = (float*)d_out;

    const int M = in_sizes[0] / D_IN;   // 16000

    __half *X16, *W1h;
    __nv_bfloat16 *W2hi, *W2lo, *h1hi, *h1lo;
    float* h2;
    cudaGetSymbolAddress((void**)&X16, g_X16);
    cudaGetSymbolAddress((void**)&W1h, g_W1);
    cudaGetSymbolAddress((void**)&W2hi, g_W2hi);
    cudaGetSymbolAddress((void**)&W2lo, g_W2lo);
    cudaGetSymbolAddress((void**)&h1hi, g_h1hi);
    cudaGetSymbolAddress((void**)&h1lo, g_h1lo);
    cudaGetSymbolAddress((void**)&h2, g_h2);

    // conversions
    {
        const size_t n4 = (size_t)M * D_IN / 4;
        conv_x_f16<<<(unsigned)((n4 + 255) / 256), 256>>>(X, X16, n4);
        dim3 tb(32, 8);
        transpose_f16<<<dim3(D_HID / 32, D_IN / 32), tb>>>(W1, W1h, D_IN, D_HID);
        transpose_split<<<dim3(D_HID / 32, D_HID / 32), tb>>>(W2, W2hi, W2lo, D_HID, D_HID);
    }

    cudaFuncSetAttribute(gemm1_f16, cudaFuncAttributeMaxDynamicSharedMemorySize, SM1_TOTAL);
    cudaFuncSetAttribute(gemm2_bf16x3, cudaFuncAttributeMaxDynamicSharedMemorySize, SM2_TOTAL);

    dim3 grid(D_HID / 128, M / 128);   // (8, 125) = 1000 CTAs
    gemm1_f16<<<grid, 512, SM1_TOTAL>>>(X16, W1h, b1, h1hi, h1lo, D_IN, D_HID);
    gemm2_bf16x3<<<grid, 512, SM2_TOTAL>>>(h1hi, h1lo, W2hi, W2lo, b2, h2, D_HID, D_HID);

    const int threads = 256;
    const int blocks = (M * 32 + threads - 1) / threads;
    heads_kernel<<<blocks, threads>>>(h2, Wc, bc, Wr, br, out, M);
}

// round 15
// speedup vs baseline: 2.6795x; 1.2168x over previous
#include <cuda_runtime.h>
#include <cuda_bf16.h>
#include <cuda_fp16.h>
#include <cstdint>
#include <cstddef>

#define D_IN  12544
#define D_HID 1024
#define MAXN  16000

// ---------------- device scratch (allocation-free rule) ----------------
__device__ __align__(1024) __half g_X16[(size_t)MAXN * D_IN];
__device__ __align__(1024) __half g_W1[(size_t)D_HID * D_IN];   // [N][K] fp16
__device__ __align__(1024) __half g_W2[(size_t)D_HID * D_HID];  // [N][K] fp16
__device__ __align__(1024) __half g_h1hi[(size_t)MAXN * D_HID];
__device__ __align__(1024) __half g_h1lo[(size_t)MAXN * D_HID];
__device__ float g_h2[(size_t)MAXN * D_HID];

// ---------------- asm helpers ----------------
__device__ __forceinline__ uint32_t smem_u32(const void* p) {
    uint32_t a;
    asm("{ .reg .u64 t; cvta.to.shared.u64 t, %1; cvt.u32.u64 %0, t; }" : "=r"(a) : "l"(p));
    return a;
}
__device__ __forceinline__ void cp16(uint32_t dst, const void* src) {
    asm volatile("cp.async.cg.shared.global [%0], [%1], 16;" :: "r"(dst), "l"(src));
}
__device__ __forceinline__ void cp_commit() {
    asm volatile("cp.async.commit_group;" ::: "memory");
}
template <int N>
__device__ __forceinline__ void cp_wait() {
    asm volatile("cp.async.wait_group %0;" :: "n"(N) : "memory");
}
__device__ __forceinline__ void ldm_x4(uint32_t* r, uint32_t addr) {
    asm volatile("ldmatrix.sync.aligned.m8n8.x4.shared.b16 {%0,%1,%2,%3}, [%4];"
                 : "=r"(r[0]), "=r"(r[1]), "=r"(r[2]), "=r"(r[3]) : "r"(addr));
}
__device__ __forceinline__ void mma_f16(float* c, const uint32_t* a, uint32_t b0, uint32_t b1) {
    asm volatile(
        "mma.sync.aligned.m16n8k16.row.col.f32.f16.f16.f32 "
        "{%0,%1,%2,%3}, {%4,%5,%6,%7}, {%8,%9}, {%0,%1,%2,%3};"
        : "+f"(c[0]), "+f"(c[1]), "+f"(c[2]), "+f"(c[3])
        : "r"(a[0]), "r"(a[1]), "r"(a[2]), "r"(a[3]), "r"(b0), "r"(b1));
}

// ---------------- common tile geometry ----------------
#define LDS       40                    // smem stride in halves (80B) - conflict free
#define TILE_B    (128 * LDS * 2)       // 10240 B per [128][32] 16-bit tile

// 512-thread loader: 512 chunks, one each
__device__ __forceinline__ void load_tile16_512(uint32_t sdst, const void* __restrict__ g,
                                                int row0, int K, int k0, int tid)
{
    const char* gb = (const char*)g + ((size_t)row0 * K + k0) * 2;
    const int r = tid >> 2;
    const int c = tid & 3;
    cp16(sdst + r * (LDS * 2) + c * 16, gb + (size_t)r * K * 2 + c * 16);
}
// 256-thread loader: 512 chunks, two each
__device__ __forceinline__ void load_tile16_256(uint32_t sdst, const void* __restrict__ g,
                                                int row0, int K, int k0, int tid)
{
    const char* gb = (const char*)g + ((size_t)row0 * K + k0) * 2;
#pragma unroll
    for (int p = 0; p < 2; p++) {
        const int r = (tid >> 2) + p * 64;
        const int c = tid & 3;
        cp16(sdst + r * (LDS * 2) + c * 16, gb + (size_t)r * K * 2 + c * 16);
    }
}

// ============================================================================
// GEMM1: h1 = relu(X @ W1^T + b1); X, W1 single fp16, 1 product.
// 256 threads, 8 warps (4M x 2N), warp tile 32x64, 2 CTAs/SM.
// 4-stage pipeline, prefetch dist 2, barrier every 2 iters.
// Epilogue writes h1 as EXACT fp16 hi/lo for GEMM2.
// ============================================================================
#define OFF1_A    0
#define OFF1_B    (TILE_B)
#define STAGE1_B  (2 * TILE_B)          // 20480
#define SM1_TOTAL (4 * STAGE1_B)        // 81920 -> 2 CTAs/SM

__global__ __launch_bounds__(256, 2)
void gemm1_f16(const __half* __restrict__ A, const __half* __restrict__ B,
               const float* __restrict__ bias,
               __half* __restrict__ Chi, __half* __restrict__ Clo,
               int K, int N)
{
    extern __shared__ char smem[];
    const uint32_t sb = smem_u32(smem);
    const int tid  = threadIdx.x;
    const int wid  = tid >> 5;
    const int lane = tid & 31;
    const int wm   = wid & 3;        // 0..3 (M)
    const int wn   = wid >> 2;       // 0..1 (N)

    const int bm = blockIdx.y * 128;
    const int bn = blockIdx.x * 128;
    const int NK = K / 32;           // 392, even

    float acc[2][8][4];
#pragma unroll
    for (int mt = 0; mt < 2; mt++)
#pragma unroll
        for (int nb = 0; nb < 8; nb++)
#pragma unroll
            for (int q = 0; q < 4; q++) acc[mt][nb][q] = 0.0f;

#pragma unroll
    for (int s = 0; s < 2; s++) {
        const uint32_t st = sb + s * STAGE1_B;
        load_tile16_256(st + OFF1_A, A, bm, K, s * 32, tid);
        load_tile16_256(st + OFF1_B, B, bn, K, s * 32, tid);
        cp_commit();
    }

    const uint32_t a_lane_off = ((lane & 15) * LDS + (lane >> 4) * 8) * 2;
    const uint32_t b_lane_off = ((((lane >> 4) * 8) + (lane & 7)) * LDS + (((lane >> 3) & 1) * 8)) * 2;
    const uint32_t a_base_off = (wm * 32) * (LDS * 2);
    const uint32_t b_base_off = (wn * 64) * (LDS * 2);

    for (int c = 0; c < NK; c++) {
        if ((c & 1) == 0) {
            cp_wait<0>();
            __syncthreads();
        }

        const int pf = c + 2;
        if (pf < NK) {
            const uint32_t st = sb + (pf & 3) * STAGE1_B;
            load_tile16_256(st + OFF1_A, A, bm, K, pf * 32, tid);
            load_tile16_256(st + OFF1_B, B, bn, K, pf * 32, tid);
        }
        cp_commit();

        const uint32_t st = sb + (c & 3) * STAGE1_B;
        const uint32_t sA = st + OFF1_A + a_base_off + a_lane_off;
        const uint32_t sB = st + OFF1_B + b_base_off + b_lane_off;

#pragma unroll
        for (int kk = 0; kk < 2; kk++) {
            const uint32_t ko = kk * 16 * 2;
            uint32_t af[2][4];
#pragma unroll
            for (int mt = 0; mt < 2; mt++)
                ldm_x4(af[mt], sA + mt * 16 * (LDS * 2) + ko);
            uint32_t bf[4][4];
#pragma unroll
            for (int pi = 0; pi < 4; pi++)
                ldm_x4(bf[pi], sB + pi * 16 * (LDS * 2) + ko);

            // 16 independent MMAs
#pragma unroll
            for (int mt = 0; mt < 2; mt++)
#pragma unroll
                for (int pi = 0; pi < 4; pi++)
#pragma unroll
                    for (int h = 0; h < 2; h++)
                        mma_f16(acc[mt][pi * 2 + h], af[mt], bf[pi][h * 2], bf[pi][h * 2 + 1]);
        }
    }

    // epilogue: bias + ReLU -> exact fp16 hi/lo
#pragma unroll
    for (int mt = 0; mt < 2; mt++) {
        const int row0 = bm + wm * 32 + mt * 16 + (lane >> 2);
#pragma unroll
        for (int nb = 0; nb < 8; nb++) {
            const int col = bn + wn * 64 + nb * 8 + (lane & 3) * 2;
            const float bx = bias[col];
            const float by = bias[col + 1];
            float y0 = fmaxf(acc[mt][nb][0] + bx, 0.0f);
            float y1 = fmaxf(acc[mt][nb][1] + by, 0.0f);
            float y2 = fmaxf(acc[mt][nb][2] + bx, 0.0f);
            float y3 = fmaxf(acc[mt][nb][3] + by, 0.0f);
            __half h0 = __float2half_rn(y0), h1 = __float2half_rn(y1);
            __half h2 = __float2half_rn(y2), h3 = __float2half_rn(y3);
            __half l0 = __float2half_rn(y0 - __half2float(h0));
            __half l1 = __float2half_rn(y1 - __half2float(h1));
            __half l2 = __float2half_rn(y2 - __half2float(h2));
            __half l3 = __float2half_rn(y3 - __half2float(h3));
            *(__half2*)(Chi + (size_t)row0 * N + col)       = __half2(h0, h1);
            *(__half2*)(Chi + (size_t)(row0 + 8) * N + col) = __half2(h2, h3);
            *(__half2*)(Clo + (size_t)row0 * N + col)       = __half2(l0, l1);
            *(__half2*)(Clo + (size_t)(row0 + 8) * N + col) = __half2(l2, l3);
        }
    }
}

// ============================================================================
// GEMM2: h2 = relu(h1 @ W2^T + b2); h1 = fp16 hi+lo (exact), W2 = fp16 single.
// 2 products/iter. 512 threads, 16 warps (4x4), warp 32x32, R13 structure.
// ============================================================================
#define OFF2_AHI  0
#define OFF2_ALO  (TILE_B)
#define OFF2_B    (2 * TILE_B)
#define STAGE2_B  (3 * TILE_B)          // 30720
#define SM2_TOTAL (4 * STAGE2_B)        // 122880

__global__ __launch_bounds__(512, 1)
void gemm2_f16x2(const __half* __restrict__ Ahi, const __half* __restrict__ Alo,
                 const __half* __restrict__ B,
                 const float* __restrict__ bias,
                 float* __restrict__ Cf,
                 int K, int N)
{
    extern __shared__ char smem[];
    const uint32_t sb = smem_u32(smem);
    const int tid  = threadIdx.x;
    const int wid  = tid >> 5;
    const int lane = tid & 31;
    const int wm   = wid & 3;
    const int wn   = wid >> 2;

    const int bm = blockIdx.y * 128;
    const int bn = blockIdx.x * 128;
    const int NK = K / 32;               // 32, even

    float acc[2][4][4];
#pragma unroll
    for (int mt = 0; mt < 2; mt++)
#pragma unroll
        for (int nb = 0; nb < 4; nb++)
#pragma unroll
            for (int q = 0; q < 4; q++) acc[mt][nb][q] = 0.0f;

#pragma unroll
    for (int s = 0; s < 2; s++) {
        const uint32_t st = sb + s * STAGE2_B;
        load_tile16_512(st + OFF2_AHI, Ahi, bm, K, s * 32, tid);
        load_tile16_512(st + OFF2_ALO, Alo, bm, K, s * 32, tid);
        load_tile16_512(st + OFF2_B,   B,   bn, K, s * 32, tid);
        cp_commit();
    }

    const uint32_t a_lane_off = ((lane & 15) * LDS + (lane >> 4) * 8) * 2;
    const uint32_t b_lane_off = ((((lane >> 4) * 8) + (lane & 7)) * LDS + (((lane >> 3) & 1) * 8)) * 2;
    const uint32_t a_base_off = (wm * 32) * (LDS * 2);
    const uint32_t b_base_off = (wn * 32) * (LDS * 2);

    for (int c = 0; c < NK; c++) {
        if ((c & 1) == 0) {
            cp_wait<0>();
            __syncthreads();
        }

        const int pf = c + 2;
        if (pf < NK) {
            const uint32_t st = sb + (pf & 3) * STAGE2_B;
            load_tile16_512(st + OFF2_AHI, Ahi, bm, K, pf * 32, tid);
            load_tile16_512(st + OFF2_ALO, Alo, bm, K, pf * 32, tid);
            load_tile16_512(st + OFF2_B,   B,   bn, K, pf * 32, tid);
        }
        cp_commit();

        const uint32_t st = sb + (c & 3) * STAGE2_B;
        const uint32_t sAh = st + OFF2_AHI + a_base_off + a_lane_off;
        const uint32_t sAl = st + OFF2_ALO + a_base_off + a_lane_off;
        const uint32_t sB  = st + OFF2_B   + b_base_off + b_lane_off;

#pragma unroll
        for (int kk = 0; kk < 2; kk++) {
            const uint32_t ko = kk * 16 * 2;
            uint32_t ah[2][4], al[2][4];
#pragma unroll
            for (int mt = 0; mt < 2; mt++) {
                ldm_x4(ah[mt], sAh + mt * 16 * (LDS * 2) + ko);
                ldm_x4(al[mt], sAl + mt * 16 * (LDS * 2) + ko);
            }
            uint32_t bf[2][4];
#pragma unroll
            for (int pi = 0; pi < 2; pi++)
                ldm_x4(bf[pi], sB + pi * 16 * (LDS * 2) + ko);

            // product 1: Ahi * B
#pragma unroll
            for (int mt = 0; mt < 2; mt++)
#pragma unroll
                for (int pi = 0; pi < 2; pi++)
#pragma unroll
                    for (int h = 0; h < 2; h++)
                        mma_f16(acc[mt][pi * 2 + h], ah[mt], bf[pi][h * 2], bf[pi][h * 2 + 1]);
            // product 2: Alo * B
#pragma unroll
            for (int mt = 0; mt < 2; mt++)
#pragma unroll
                for (int pi = 0; pi < 2; pi++)
#pragma unroll
                    for (int h = 0; h < 2; h++)
                        mma_f16(acc[mt][pi * 2 + h], al[mt], bf[pi][h * 2], bf[pi][h * 2 + 1]);
        }
    }

#pragma unroll
    for (int mt = 0; mt < 2; mt++) {
        const int row0 = bm + wm * 32 + mt * 16 + (lane >> 2);
#pragma unroll
        for (int nb = 0; nb < 4; nb++) {
            const int col = bn + wn * 32 + nb * 8 + (lane & 3) * 2;
            const float bx = bias[col];
            const float by = bias[col + 1];
            float2 v0, v1;
            v0.x = fmaxf(acc[mt][nb][0] + bx, 0.0f);
            v0.y = fmaxf(acc[mt][nb][1] + by, 0.0f);
            v1.x = fmaxf(acc[mt][nb][2] + bx, 0.0f);
            v1.y = fmaxf(acc[mt][nb][3] + by, 0.0f);
            *(float2*)(Cf + (size_t)row0 * N + col)       = v0;
            *(float2*)(Cf + (size_t)(row0 + 8) * N + col) = v1;
        }
    }
}

// ---------------- conversion kernels ----------------
__global__ __launch_bounds__(256)
void conv_x_f16(const float* __restrict__ in, __half* __restrict__ out, size_t n4)
{
    size_t i = (size_t)blockIdx.x * blockDim.x + threadIdx.x;
    if (i >= n4) return;
    float4 v = ((const float4*)in)[i];
    ((__half2*)out)[i * 2 + 0] = __half2(__float2half_rn(v.x), __float2half_rn(v.y));
    ((__half2*)out)[i * 2 + 1] = __half2(__float2half_rn(v.z), __float2half_rn(v.w));
}

// [K][N] fp32 -> [N][K] fp16 single
__global__ __launch_bounds__(256)
void transpose_f16(const float* __restrict__ in, __half* __restrict__ out, int K, int N)
{
    __shared__ float t[32][33];
    const int k0 = blockIdx.y * 32;
    const int n0 = blockIdx.x * 32;
    const int tx = threadIdx.x;
    const int ty = threadIdx.y;
#pragma unroll
    for (int r = 0; r < 4; r++) {
        const int k = k0 + ty * 4 + r;
        t[ty * 4 + r][tx] = in[(size_t)k * N + n0 + tx];
    }
    __syncthreads();
#pragma unroll
    for (int r = 0; r < 4; r++) {
        const int n = n0 + ty * 4 + r;
        out[(size_t)n * K + k0 + tx] = __float2half_rn(t[tx][ty * 4 + r]);
    }
}

// ---------------- heads ----------------
__global__ __launch_bounds__(256)
void heads_kernel(const float* __restrict__ H,
                  const float* __restrict__ Wc, const float* __restrict__ bc,
                  const float* __restrict__ Wr, const float* __restrict__ br,
                  float* __restrict__ out, int M)
{
    const int warp = (blockIdx.x * blockDim.x + threadIdx.x) >> 5;
    const int lane = threadIdx.x & 31;
    if (warp >= M) return;

    const float* __restrict__ h = H + (size_t)warp * D_HID;
    float acc[16];
#pragma unroll
    for (int c = 0; c < 16; c++) acc[c] = 0.0f;

    for (int k = lane; k < D_HID; k += 32) {
        const float x = h[k];
        const float* wc = Wc + (size_t)k * 4;
#pragma unroll
        for (int c = 0; c < 4; c++) acc[c] = fmaf(x, wc[c], acc[c]);
        const float* wr = Wr + (size_t)k * 12;
#pragma unroll
        for (int c = 0; c < 12; c++) acc[4 + c] = fmaf(x, wr[c], acc[4 + c]);
    }
#pragma unroll
    for (int c = 0; c < 16; c++)
#pragma unroll
        for (int off = 16; off > 0; off >>= 1)
            acc[c] += __shfl_xor_sync(0xffffffffu, acc[c], off);

    if (lane < 4) {
        out[(size_t)warp * 4 + lane] = acc[lane] + bc[lane];
    } else if (lane < 16) {
        out[(size_t)M * 4 + (size_t)warp * 12 + (lane - 4)] = acc[lane] + br[lane - 4];
    }
}

// ---------------- host ----------------
extern "C" void kernel_launch(void* const* d_in, const int* in_sizes, int n_in,
                              void* d_out, int out_size)
{
    const float* X  = (const float*)d_in[0];
    const float* W1 = (const float*)d_in[1];
    const float* b1 = (const float*)d_in[2];
    const float* W2 = (const float*)d_in[3];
    const float* b2 = (const float*)d_in[4];
    const float* Wc = (const float*)d_in[5];
    const float* bc = (const float*)d_in[6];
    const float* Wr = (const float*)d_in[7];
    const float* br = (const float*)d_in[8];
    float* out = (float*)d_out;

    const int M = in_sizes[0] / D_IN;   // 16000

    __half *X16, *W1h, *W2h, *h1hi, *h1lo;
    float* h2;
    cudaGetSymbolAddress((void**)&X16, g_X16);
    cudaGetSymbolAddress((void**)&W1h, g_W1);
    cudaGetSymbolAddress((void**)&W2h, g_W2);
    cudaGetSymbolAddress((void**)&h1hi, g_h1hi);
    cudaGetSymbolAddress((void**)&h1lo, g_h1lo);
    cudaGetSymbolAddress((void**)&h2, g_h2);

    // conversions
    {
        const size_t n4 = (size_t)M * D_IN / 4;
        conv_x_f16<<<(unsigned)((n4 + 255) / 256), 256>>>(X, X16, n4);
        dim3 tb(32, 8);
        transpose_f16<<<dim3(D_HID / 32, D_IN / 32), tb>>>(W1, W1h, D_IN, D_HID);
        transpose_f16<<<dim3(D_HID / 32, D_HID / 32), tb>>>(W2, W2h, D_HID, D_HID);
    }

    cudaFuncSetAttribute(gemm1_f16, cudaFuncAttributeMaxDynamicSharedMemorySize, SM1_TOTAL);
    cudaFuncSetAttribute(gemm2_f16x2, cudaFuncAttributeMaxDynamicSharedMemorySize, SM2_TOTAL);

    dim3 grid(D_HID / 128, M / 128);   // (8, 125) = 1000 CTAs
    gemm1_f16<<<grid, 256, SM1_TOTAL>>>(X16, W1h, b1, h1hi, h1lo, D_IN, D_HID);
    gemm2_f16x2<<<grid, 512, SM2_TOTAL>>>(h1hi, h1lo, W2h, b2, h2, D_HID, D_HID);

    const int threads = 256;
    const int blocks = (M * 32 + threads - 1) / threads;
    heads_kernel<<<blocks, threads>>>(h2, Wc, bc, Wr, br, out, M);
}

// round 16
// speedup vs baseline: 2.7608x; 1.0303x over previous
#include <cuda_runtime.h>
#include <cuda_bf16.h>
#include <cuda_fp16.h>
#include <cstdint>
#include <cstddef>

#define D_IN  12544
#define D_HID 1024
#define MAXN  16000

// ---------------- device scratch (allocation-free rule) ----------------
__device__ __align__(1024) __half g_X16[(size_t)MAXN * D_IN];
__device__ __align__(1024) __half g_W1[(size_t)D_HID * D_IN];   // [N][K] fp16
__device__ __align__(1024) __half g_W2[(size_t)D_HID * D_HID];  // [N][K] fp16
__device__ __align__(1024) float  g_h1p0[(size_t)MAXN * D_HID]; // K-slice partials
__device__ __align__(1024) float  g_h1p1[(size_t)MAXN * D_HID];
__device__ __align__(1024) __half g_h1[(size_t)MAXN * D_HID];   // fp16 single
__device__ float g_h2[(size_t)MAXN * D_HID];

// ---------------- asm helpers ----------------
__device__ __forceinline__ uint32_t smem_u32(const void* p) {
    uint32_t a;
    asm("{ .reg .u64 t; cvta.to.shared.u64 t, %1; cvt.u32.u64 %0, t; }" : "=r"(a) : "l"(p));
    return a;
}
__device__ __forceinline__ void cp16(uint32_t dst, const void* src) {
    asm volatile("cp.async.cg.shared.global [%0], [%1], 16;" :: "r"(dst), "l"(src));
}
__device__ __forceinline__ void cp_commit() {
    asm volatile("cp.async.commit_group;" ::: "memory");
}
template <int N>
__device__ __forceinline__ void cp_wait() {
    asm volatile("cp.async.wait_group %0;" :: "n"(N) : "memory");
}
__device__ __forceinline__ void ldm_x4(uint32_t* r, uint32_t addr) {
    asm volatile("ldmatrix.sync.aligned.m8n8.x4.shared.b16 {%0,%1,%2,%3}, [%4];"
                 : "=r"(r[0]), "=r"(r[1]), "=r"(r[2]), "=r"(r[3]) : "r"(addr));
}
__device__ __forceinline__ void mma_f16(float* c, const uint32_t* a, uint32_t b0, uint32_t b1) {
    asm volatile(
        "mma.sync.aligned.m16n8k16.row.col.f32.f16.f16.f32 "
        "{%0,%1,%2,%3}, {%4,%5,%6,%7}, {%8,%9}, {%0,%1,%2,%3};"
        : "+f"(c[0]), "+f"(c[1]), "+f"(c[2]), "+f"(c[3])
        : "r"(a[0]), "r"(a[1]), "r"(a[2]), "r"(a[3]), "r"(b0), "r"(b1));
}

// ---------------- common tile geometry ----------------
#define LDS       40                    // smem stride in halves (80B) - conflict free
#define TILE_B    (128 * LDS * 2)       // 10240 B per [128][32] fp16 tile
#define OFF_A     0
#define OFF_B     (TILE_B)
#define STAGE_B   (2 * TILE_B)          // 20480
#define SM_TOTAL  (4 * STAGE_B)         // 81920 -> 2 CTAs/SM

// 256-thread loader: 512 chunks of 16B, two per thread
__device__ __forceinline__ void load_tile16(uint32_t sdst, const void* __restrict__ g,
                                            int row0, int K, int k0, int tid)
{
    const char* gb = (const char*)g + ((size_t)row0 * K + k0) * 2;
#pragma unroll
    for (int p = 0; p < 2; p++) {
        const int r = (tid >> 2) + p * 64;
        const int c = tid & 3;
        cp16(sdst + r * (LDS * 2) + c * 16, gb + (size_t)r * K * 2 + c * 16);
    }
}

// ============================================================================
// Single-product fp16 GEMM tile kernel.
// CTA 128x128, 256 threads, 8 warps (4M x 2N), warp tile 32x64, 2 CTAs/SM.
// 4-stage cp.async pipeline, prefetch dist 2, barrier every 2 iters.
// EPI=0: write raw fp32 accumulators (K-slice partial, no bias/relu).
// EPI=1: bias + ReLU -> fp32 out.
// ============================================================================
template <int EPI>
__global__ __launch_bounds__(256, 2)
void gemm_f16s(const __half* __restrict__ A, const __half* __restrict__ B,
               const float* __restrict__ bias,
               float* __restrict__ Cout,
               int Kfull, int NKiters, int N)
{
    extern __shared__ char smem[];
    const uint32_t sb = smem_u32(smem);
    const int tid  = threadIdx.x;
    const int wid  = tid >> 5;
    const int lane = tid & 31;
    const int wm   = wid & 3;        // 0..3 (M)
    const int wn   = wid >> 2;       // 0..1 (N)

    const int bm = blockIdx.y * 128;
    const int bn = blockIdx.x * 128;

    float acc[2][8][4];
#pragma unroll
    for (int mt = 0; mt < 2; mt++)
#pragma unroll
        for (int nb = 0; nb < 8; nb++)
#pragma unroll
            for (int q = 0; q < 4; q++) acc[mt][nb][q] = 0.0f;

#pragma unroll
    for (int s = 0; s < 2; s++) {
        const uint32_t st = sb + s * STAGE_B;
        load_tile16(st + OFF_A, A, bm, Kfull, s * 32, tid);
        load_tile16(st + OFF_B, B, bn, Kfull, s * 32, tid);
        cp_commit();
    }

    const uint32_t a_lane_off = ((lane & 15) * LDS + (lane >> 4) * 8) * 2;
    const uint32_t b_lane_off = ((((lane >> 4) * 8) + (lane & 7)) * LDS + (((lane >> 3) & 1) * 8)) * 2;
    const uint32_t a_base_off = (wm * 32) * (LDS * 2);
    const uint32_t b_base_off = (wn * 64) * (LDS * 2);

    for (int c = 0; c < NKiters; c++) {
        if ((c & 1) == 0) {
            cp_wait<0>();
            __syncthreads();
        }

        const int pf = c + 2;
        if (pf < NKiters) {
            const uint32_t st = sb + (pf & 3) * STAGE_B;
            load_tile16(st + OFF_A, A, bm, Kfull, pf * 32, tid);
            load_tile16(st + OFF_B, B, bn, Kfull, pf * 32, tid);
        }
        cp_commit();

        const uint32_t st = sb + (c & 3) * STAGE_B;
        const uint32_t sA = st + OFF_A + a_base_off + a_lane_off;
        const uint32_t sB = st + OFF_B + b_base_off + b_lane_off;

#pragma unroll
        for (int kk = 0; kk < 2; kk++) {
            const uint32_t ko = kk * 16 * 2;
            uint32_t af[2][4];
#pragma unroll
            for (int mt = 0; mt < 2; mt++)
                ldm_x4(af[mt], sA + mt * 16 * (LDS * 2) + ko);
            uint32_t bf[4][4];
#pragma unroll
            for (int pi = 0; pi < 4; pi++)
                ldm_x4(bf[pi], sB + pi * 16 * (LDS * 2) + ko);

            // 16 independent MMAs
#pragma unroll
            for (int mt = 0; mt < 2; mt++)
#pragma unroll
                for (int pi = 0; pi < 4; pi++)
#pragma unroll
                    for (int h = 0; h < 2; h++)
                        mma_f16(acc[mt][pi * 2 + h], af[mt], bf[pi][h * 2], bf[pi][h * 2 + 1]);
        }
    }

    // ---------------- epilogue ----------------
#pragma unroll
    for (int mt = 0; mt < 2; mt++) {
        const int row0 = bm + wm * 32 + mt * 16 + (lane >> 2);
#pragma unroll
        for (int nb = 0; nb < 8; nb++) {
            const int col = bn + wn * 64 + nb * 8 + (lane & 3) * 2;
            float2 v0, v1;
            if (EPI) {
                const float bx = bias[col];
                const float by = bias[col + 1];
                v0.x = fmaxf(acc[mt][nb][0] + bx, 0.0f);
                v0.y = fmaxf(acc[mt][nb][1] + by, 0.0f);
                v1.x = fmaxf(acc[mt][nb][2] + bx, 0.0f);
                v1.y = fmaxf(acc[mt][nb][3] + by, 0.0f);
            } else {
                v0.x = acc[mt][nb][0];
                v0.y = acc[mt][nb][1];
                v1.x = acc[mt][nb][2];
                v1.y = acc[mt][nb][3];
            }
            *(float2*)(Cout + (size_t)row0 * N + col)       = v0;
            *(float2*)(Cout + (size_t)(row0 + 8) * N + col) = v1;
        }
    }
}

// ---------------- combine: h1 = fp16(relu(p0 + p1 + bias)) ----------------
__global__ __launch_bounds__(256)
void combine_h1(const float* __restrict__ p0, const float* __restrict__ p1,
                const float* __restrict__ bias, __half* __restrict__ h1, size_t n4)
{
    size_t i = (size_t)blockIdx.x * blockDim.x + threadIdx.x;
    if (i >= n4) return;
    float4 a = ((const float4*)p0)[i];
    float4 b = ((const float4*)p1)[i];
    float4 bv = ((const float4*)bias)[i & (D_HID / 4 - 1)];
    float y0 = fmaxf(a.x + b.x + bv.x, 0.0f);
    float y1 = fmaxf(a.y + b.y + bv.y, 0.0f);
    float y2 = fmaxf(a.z + b.z + bv.z, 0.0f);
    float y3 = fmaxf(a.w + b.w + bv.w, 0.0f);
    ((__half2*)h1)[i * 2 + 0] = __half2(__float2half_rn(y0), __float2half_rn(y1));
    ((__half2*)h1)[i * 2 + 1] = __half2(__float2half_rn(y2), __float2half_rn(y3));
}

// ---------------- conversion kernels ----------------
__global__ __launch_bounds__(256)
void conv_x_f16(const float* __restrict__ in, __half* __restrict__ out, size_t n4)
{
    size_t i = (size_t)blockIdx.x * blockDim.x + threadIdx.x;
    if (i >= n4) return;
    float4 v = ((const float4*)in)[i];
    ((__half2*)out)[i * 2 + 0] = __half2(__float2half_rn(v.x), __float2half_rn(v.y));
    ((__half2*)out)[i * 2 + 1] = __half2(__float2half_rn(v.z), __float2half_rn(v.w));
}

// [K][N] fp32 -> [N][K] fp16 single
__global__ __launch_bounds__(256)
void transpose_f16(const float* __restrict__ in, __half* __restrict__ out, int K, int N)
{
    __shared__ float t[32][33];
    const int k0 = blockIdx.y * 32;
    const int n0 = blockIdx.x * 32;
    const int tx = threadIdx.x;
    const int ty = threadIdx.y;
#pragma unroll
    for (int r = 0; r < 4; r++) {
        const int k = k0 + ty * 4 + r;
        t[ty * 4 + r][tx] = in[(size_t)k * N + n0 + tx];
    }
    __syncthreads();
#pragma unroll
    for (int r = 0; r < 4; r++) {
        const int n = n0 + ty * 4 + r;
        out[(size_t)n * K + k0 + tx] = __float2half_rn(t[tx][ty * 4 + r]);
    }
}

// ---------------- heads ----------------
__global__ __launch_bounds__(256)
void heads_kernel(const float* __restrict__ H,
                  const float* __restrict__ Wc, const float* __restrict__ bc,
                  const float* __restrict__ Wr, const float* __restrict__ br,
                  float* __restrict__ out, int M)
{
    const int warp = (blockIdx.x * blockDim.x + threadIdx.x) >> 5;
    const int lane = threadIdx.x & 31;
    if (warp >= M) return;

    const float* __restrict__ h = H + (size_t)warp * D_HID;
    float acc[16];
#pragma unroll
    for (int c = 0; c < 16; c++) acc[c] = 0.0f;

    for (int k = lane; k < D_HID; k += 32) {
        const float x = h[k];
        const float* wc = Wc + (size_t)k * 4;
#pragma unroll
        for (int c = 0; c < 4; c++) acc[c] = fmaf(x, wc[c], acc[c]);
        const float* wr = Wr + (size_t)k * 12;
#pragma unroll
        for (int c = 0; c < 12; c++) acc[4 + c] = fmaf(x, wr[c], acc[4 + c]);
    }
#pragma unroll
    for (int c = 0; c < 16; c++)
#pragma unroll
        for (int off = 16; off > 0; off >>= 1)
            acc[c] += __shfl_xor_sync(0xffffffffu, acc[c], off);

    if (lane < 4) {
        out[(size_t)warp * 4 + lane] = acc[lane] + bc[lane];
    } else if (lane < 16) {
        out[(size_t)M * 4 + (size_t)warp * 12 + (lane - 4)] = acc[lane] + br[lane - 4];
    }
}

// ---------------- host ----------------
extern "C" void kernel_launch(void* const* d_in, const int* in_sizes, int n_in,
                              void* d_out, int out_size)
{
    const float* X  = (const float*)d_in[0];
    const float* W1 = (const float*)d_in[1];
    const float* b1 = (const float*)d_in[2];
    const float* W2 = (const float*)d_in[3];
    const float* b2 = (const float*)d_in[4];
    const float* Wc = (const float*)d_in[5];
    const float* bc = (const float*)d_in[6];
    const float* Wr = (const float*)d_in[7];
    const float* br = (const float*)d_in[8];
    float* out = (float*)d_out;

    const int M = in_sizes[0] / D_IN;   // 16000

    __half *X16, *W1h, *W2h, *h1;
    float *h1p0, *h1p1, *h2;
    cudaGetSymbolAddress((void**)&X16, g_X16);
    cudaGetSymbolAddress((void**)&W1h, g_W1);
    cudaGetSymbolAddress((void**)&W2h, g_W2);
    cudaGetSymbolAddress((void**)&h1p0, g_h1p0);
    cudaGetSymbolAddress((void**)&h1p1, g_h1p1);
    cudaGetSymbolAddress((void**)&h1, g_h1);
    cudaGetSymbolAddress((void**)&h2, g_h2);

    // conversions
    {
        const size_t n4 = (size_t)M * D_IN / 4;
        conv_x_f16<<<(unsigned)((n4 + 255) / 256), 256>>>(X, X16, n4);
        dim3 tb(32, 8);
        transpose_f16<<<dim3(D_HID / 32, D_IN / 32), tb>>>(W1, W1h, D_IN, D_HID);
        transpose_f16<<<dim3(D_HID / 32, D_HID / 32), tb>>>(W2, W2h, D_HID, D_HID);
    }

    cudaFuncSetAttribute(gemm_f16s<0>, cudaFuncAttributeMaxDynamicSharedMemorySize, SM_TOTAL);
    cudaFuncSetAttribute(gemm_f16s<1>, cudaFuncAttributeMaxDynamicSharedMemorySize, SM_TOTAL);

    // GEMM1: K split into 2 half-K launches (CTAs from the second launch fill SMs
    // as the first drains -> wave-quantization tail smoothed).
    {
        dim3 grid(D_HID / 128, M / 128);      // 1000 CTAs each
        const int NKslice = (D_IN / 32) / 2;  // 196 iterations (even)
        const int Khalf = NKslice * 32;       // 6272
        gemm_f16s<0><<<grid, 256, SM_TOTAL>>>(X16, W1h, nullptr, h1p0, D_IN, NKslice, D_HID);
        gemm_f16s<0><<<grid, 256, SM_TOTAL>>>(X16 + Khalf, W1h + Khalf,
                                              nullptr, h1p1, D_IN, NKslice, D_HID);
    }

    // combine partials -> h1 fp16 (bias + relu)
    {
        const size_t n4 = (size_t)M * D_HID / 4;
        combine_h1<<<(unsigned)((n4 + 255) / 256), 256>>>(h1p0, h1p1, b1, h1, n4);
    }

    // GEMM2: single product fp16, bias + relu -> fp32 h2
    {
        dim3 grid(D_HID / 128, M / 128);      // 1000 CTAs
        gemm_f16s<1><<<grid, 256, SM_TOTAL>>>(h1, W2h, b2, h2, D_HID, D_HID / 32, D_HID);
    }

    const int threads = 256;
    const int blocks = (M * 32 + threads - 1) / threads;
    heads_kernel<<<blocks, threads>>>(h2, Wc, bc, Wr, br, out, M);
}

// round 17
// speedup vs baseline: 2.7691x; 1.0030x over previous
#include <cuda_runtime.h>
#include <cuda_bf16.h>
#include <cuda_fp16.h>
#include <cstdint>
#include <cstddef>

#define D_IN  12544
#define D_HID 1024
#define MAXN  16000

// ---------------- device scratch (allocation-free rule) ----------------
__device__ __align__(1024) __half g_X16[(size_t)MAXN * D_IN];
__device__ __align__(1024) __half g_W1[(size_t)D_HID * D_IN];   // [N][K] fp16
__device__ __align__(1024) __half g_W2[(size_t)D_HID * D_HID];  // [N][K] fp16
__device__ __align__(1024) float  g_h1p[(size_t)2 * MAXN * D_HID]; // K-slice partials (z=0,1)
__device__ __align__(1024) __half g_h1[(size_t)MAXN * D_HID];   // fp16 single
__device__ float g_h2[(size_t)MAXN * D_HID];

// ---------------- asm helpers ----------------
__device__ __forceinline__ uint32_t smem_u32(const void* p) {
    uint32_t a;
    asm("{ .reg .u64 t; cvta.to.shared.u64 t, %1; cvt.u32.u64 %0, t; }" : "=r"(a) : "l"(p));
    return a;
}
__device__ __forceinline__ void cp16(uint32_t dst, const void* src) {
    asm volatile("cp.async.cg.shared.global [%0], [%1], 16;" :: "r"(dst), "l"(src));
}
__device__ __forceinline__ void cp_commit() {
    asm volatile("cp.async.commit_group;" ::: "memory");
}
template <int N>
__device__ __forceinline__ void cp_wait() {
    asm volatile("cp.async.wait_group %0;" :: "n"(N) : "memory");
}
__device__ __forceinline__ void ldm_x4(uint32_t* r, uint32_t addr) {
    asm volatile("ldmatrix.sync.aligned.m8n8.x4.shared.b16 {%0,%1,%2,%3}, [%4];"
                 : "=r"(r[0]), "=r"(r[1]), "=r"(r[2]), "=r"(r[3]) : "r"(addr));
}
__device__ __forceinline__ void mma_f16(float* c, const uint32_t* a, uint32_t b0, uint32_t b1) {
    asm volatile(
        "mma.sync.aligned.m16n8k16.row.col.f32.f16.f16.f32 "
        "{%0,%1,%2,%3}, {%4,%5,%6,%7}, {%8,%9}, {%0,%1,%2,%3};"
        : "+f"(c[0]), "+f"(c[1]), "+f"(c[2]), "+f"(c[3])
        : "r"(a[0]), "r"(a[1]), "r"(a[2]), "r"(a[3]), "r"(b0), "r"(b1));
}

// ---------------- common tile geometry ----------------
#define LDS       40                    // smem stride in halves (80B) - conflict free
#define TILE_B    (128 * LDS * 2)       // 10240 B per [128][32] fp16 tile
#define OFF_A     0
#define OFF_B     (TILE_B)
#define STAGE_B   (2 * TILE_B)          // 20480
#define SM_TOTAL  (4 * STAGE_B)         // 81920 -> 2 CTAs/SM

// 256-thread loader: 512 chunks of 16B, two per thread
__device__ __forceinline__ void load_tile16(uint32_t sdst, const void* __restrict__ g,
                                            int row0, int K, int k0, int tid)
{
    const char* gb = (const char*)g + ((size_t)row0 * K + k0) * 2;
#pragma unroll
    for (int p = 0; p < 2; p++) {
        const int r = (tid >> 2) + p * 64;
        const int c = tid & 3;
        cp16(sdst + r * (LDS * 2) + c * 16, gb + (size_t)r * K * 2 + c * 16);
    }
}

// ============================================================================
// Single-product fp16 GEMM tile kernel with K-slicing via blockIdx.z.
// CTA 128x128, 256 threads, 8 warps (4M x 2N), warp tile 32x64, 2 CTAs/SM.
// 4-stage cp.async pipeline, prefetch dist 2, barrier every 2 iters.
// Slice z covers K range [z*NKiters*32, (z+1)*NKiters*32) and writes to
// Cout + z*partStride.
// EPI=0: raw fp32 partial (no bias/relu). EPI=1: bias + ReLU fp32 out.
// ============================================================================
template <int EPI>
__global__ __launch_bounds__(256, 2)
void gemm_f16s(const __half* __restrict__ A, const __half* __restrict__ B,
               const float* __restrict__ bias,
               float* __restrict__ Cout, size_t partStride,
               int Kfull, int NKiters, int N)
{
    extern __shared__ char smem[];
    const uint32_t sb = smem_u32(smem);
    const int tid  = threadIdx.x;
    const int wid  = tid >> 5;
    const int lane = tid & 31;
    const int wm   = wid & 3;        // 0..3 (M)
    const int wn   = wid >> 2;       // 0..1 (N)

    const int bm = blockIdx.y * 128;
    const int bn = blockIdx.x * 128;
    const int kBase = blockIdx.z * NKiters * 32;
    float* __restrict__ C = Cout + (size_t)blockIdx.z * partStride;

    float acc[2][8][4];
#pragma unroll
    for (int mt = 0; mt < 2; mt++)
#pragma unroll
        for (int nb = 0; nb < 8; nb++)
#pragma unroll
            for (int q = 0; q < 4; q++) acc[mt][nb][q] = 0.0f;

#pragma unroll
    for (int s = 0; s < 2; s++) {
        const uint32_t st = sb + s * STAGE_B;
        load_tile16(st + OFF_A, A, bm, Kfull, kBase + s * 32, tid);
        load_tile16(st + OFF_B, B, bn, Kfull, kBase + s * 32, tid);
        cp_commit();
    }

    const uint32_t a_lane_off = ((lane & 15) * LDS + (lane >> 4) * 8) * 2;
    const uint32_t b_lane_off = ((((lane >> 4) * 8) + (lane & 7)) * LDS + (((lane >> 3) & 1) * 8)) * 2;
    const uint32_t a_base_off = (wm * 32) * (LDS * 2);
    const uint32_t b_base_off = (wn * 64) * (LDS * 2);

    for (int c = 0; c < NKiters; c++) {
        if ((c & 1) == 0) {
            cp_wait<0>();
            __syncthreads();
        }

        const int pf = c + 2;
        if (pf < NKiters) {
            const uint32_t st = sb + (pf & 3) * STAGE_B;
            load_tile16(st + OFF_A, A, bm, Kfull, kBase + pf * 32, tid);
            load_tile16(st + OFF_B, B, bn, Kfull, kBase + pf * 32, tid);
        }
        cp_commit();

        const uint32_t st = sb + (c & 3) * STAGE_B;
        const uint32_t sA = st + OFF_A + a_base_off + a_lane_off;
        const uint32_t sB = st + OFF_B + b_base_off + b_lane_off;

#pragma unroll
        for (int kk = 0; kk < 2; kk++) {
            const uint32_t ko = kk * 16 * 2;
            uint32_t af[2][4];
#pragma unroll
            for (int mt = 0; mt < 2; mt++)
                ldm_x4(af[mt], sA + mt * 16 * (LDS * 2) + ko);
            uint32_t bf[4][4];
#pragma unroll
            for (int pi = 0; pi < 4; pi++)
                ldm_x4(bf[pi], sB + pi * 16 * (LDS * 2) + ko);

            // 16 independent MMAs
#pragma unroll
            for (int mt = 0; mt < 2; mt++)
#pragma unroll
                for (int pi = 0; pi < 4; pi++)
#pragma unroll
                    for (int h = 0; h < 2; h++)
                        mma_f16(acc[mt][pi * 2 + h], af[mt], bf[pi][h * 2], bf[pi][h * 2 + 1]);
        }
    }

    // ---------------- epilogue ----------------
#pragma unroll
    for (int mt = 0; mt < 2; mt++) {
        const int row0 = bm + wm * 32 + mt * 16 + (lane >> 2);
#pragma unroll
        for (int nb = 0; nb < 8; nb++) {
            const int col = bn + wn * 64 + nb * 8 + (lane & 3) * 2;
            float2 v0, v1;
            if (EPI) {
                const float bx = bias[col];
                const float by = bias[col + 1];
                v0.x = fmaxf(acc[mt][nb][0] + bx, 0.0f);
                v0.y = fmaxf(acc[mt][nb][1] + by, 0.0f);
                v1.x = fmaxf(acc[mt][nb][2] + bx, 0.0f);
                v1.y = fmaxf(acc[mt][nb][3] + by, 0.0f);
            } else {
                v0.x = acc[mt][nb][0];
                v0.y = acc[mt][nb][1];
                v1.x = acc[mt][nb][2];
                v1.y = acc[mt][nb][3];
            }
            *(float2*)(C + (size_t)row0 * N + col)       = v0;
            *(float2*)(C + (size_t)(row0 + 8) * N + col) = v1;
        }
    }
}

// ---------------- combine: h1 = fp16(relu(p0 + p1 + bias)) ----------------
__global__ __launch_bounds__(256)
void combine_h1(const float* __restrict__ p0, const float* __restrict__ p1,
                const float* __restrict__ bias, __half* __restrict__ h1, size_t n4)
{
    size_t i = (size_t)blockIdx.x * blockDim.x + threadIdx.x;
    if (i >= n4) return;
    float4 a = ((const float4*)p0)[i];
    float4 b = ((const float4*)p1)[i];
    float4 bv = ((const float4*)bias)[i & (D_HID / 4 - 1)];
    float y0 = fmaxf(a.x + b.x + bv.x, 0.0f);
    float y1 = fmaxf(a.y + b.y + bv.y, 0.0f);
    float y2 = fmaxf(a.z + b.z + bv.z, 0.0f);
    float y3 = fmaxf(a.w + b.w + bv.w, 0.0f);
    ((__half2*)h1)[i * 2 + 0] = __half2(__float2half_rn(y0), __float2half_rn(y1));
    ((__half2*)h1)[i * 2 + 1] = __half2(__float2half_rn(y2), __float2half_rn(y3));
}

// ---------------- conversion kernels ----------------
__global__ __launch_bounds__(256)
void conv_x_f16(const float* __restrict__ in, __half* __restrict__ out, size_t n4)
{
    size_t i = (size_t)blockIdx.x * blockDim.x + threadIdx.x;
    if (i >= n4) return;
    float4 v = ((const float4*)in)[i];
    ((__half2*)out)[i * 2 + 0] = __half2(__float2half_rn(v.x), __float2half_rn(v.y));
    ((__half2*)out)[i * 2 + 1] = __half2(__float2half_rn(v.z), __float2half_rn(v.w));
}

// [K][N] fp32 -> [N][K] fp16 single
__global__ __launch_bounds__(256)
void transpose_f16(const float* __restrict__ in, __half* __restrict__ out, int K, int N)
{
    __shared__ float t[32][33];
    const int k0 = blockIdx.y * 32;
    const int n0 = blockIdx.x * 32;
    const int tx = threadIdx.x;
    const int ty = threadIdx.y;
#pragma unroll
    for (int r = 0; r < 4; r++) {
        const int k = k0 + ty * 4 + r;
        t[ty * 4 + r][tx] = in[(size_t)k * N + n0 + tx];
    }
    __syncthreads();
#pragma unroll
    for (int r = 0; r < 4; r++) {
        const int n = n0 + ty * 4 + r;
        out[(size_t)n * K + k0 + tx] = __float2half_rn(t[tx][ty * 4 + r]);
    }
}

// ---------------- heads ----------------
__global__ __launch_bounds__(256)
void heads_kernel(const float* __restrict__ H,
                  const float* __restrict__ Wc, const float* __restrict__ bc,
                  const float* __restrict__ Wr, const float* __restrict__ br,
                  float* __restrict__ out, int M)
{
    const int warp = (blockIdx.x * blockDim.x + threadIdx.x) >> 5;
    const int lane = threadIdx.x & 31;
    if (warp >= M) return;

    const float* __restrict__ h = H + (size_t)warp * D_HID;
    float acc[16];
#pragma unroll
    for (int c = 0; c < 16; c++) acc[c] = 0.0f;

    for (int k = lane; k < D_HID; k += 32) {
        const float x = h[k];
        const float* wc = Wc + (size_t)k * 4;
#pragma unroll
        for (int c = 0; c < 4; c++) acc[c] = fmaf(x, wc[c], acc[c]);
        const float* wr = Wr + (size_t)k * 12;
#pragma unroll
        for (int c = 0; c < 12; c++) acc[4 + c] = fmaf(x, wr[c], acc[4 + c]);
    }
#pragma unroll
    for (int c = 0; c < 16; c++)
#pragma unroll
        for (int off = 16; off > 0; off >>= 1)
            acc[c] += __shfl_xor_sync(0xffffffffu, acc[c], off);

    if (lane < 4) {
        out[(size_t)warp * 4 + lane] = acc[lane] + bc[lane];
    } else if (lane < 16) {
        out[(size_t)M * 4 + (size_t)warp * 12 + (lane - 4)] = acc[lane] + br[lane - 4];
    }
}

// ---------------- host ----------------
extern "C" void kernel_launch(void* const* d_in, const int* in_sizes, int n_in,
                              void* d_out, int out_size)
{
    const float* X  = (const float*)d_in[0];
    const float* W1 = (const float*)d_in[1];
    const float* b1 = (const float*)d_in[2];
    const float* W2 = (const float*)d_in[3];
    const float* b2 = (const float*)d_in[4];
    const float* Wc = (const float*)d_in[5];
    const float* bc = (const float*)d_in[6];
    const float* Wr = (const float*)d_in[7];
    const float* br = (const float*)d_in[8];
    float* out = (float*)d_out;

    const int M = in_sizes[0] / D_IN;   // 16000

    __half *X16, *W1h, *W2h, *h1;
    float *h1p, *h2;
    cudaGetSymbolAddress((void**)&X16, g_X16);
    cudaGetSymbolAddress((void**)&W1h, g_W1);
    cudaGetSymbolAddress((void**)&W2h, g_W2);
    cudaGetSymbolAddress((void**)&h1p, g_h1p);
    cudaGetSymbolAddress((void**)&h1, g_h1);
    cudaGetSymbolAddress((void**)&h2, g_h2);

    const size_t partStride = (size_t)M * D_HID;

    // conversions
    {
        const size_t n4 = (size_t)M * D_IN / 4;
        conv_x_f16<<<(unsigned)((n4 + 255) / 256), 256>>>(X, X16, n4);
        dim3 tb(32, 8);
        transpose_f16<<<dim3(D_HID / 32, D_IN / 32), tb>>>(W1, W1h, D_IN, D_HID);
        transpose_f16<<<dim3(D_HID / 32, D_HID / 32), tb>>>(W2, W2h, D_HID, D_HID);
    }

    cudaFuncSetAttribute(gemm_f16s<0>, cudaFuncAttributeMaxDynamicSharedMemorySize, SM_TOTAL);
    cudaFuncSetAttribute(gemm_f16s<1>, cudaFuncAttributeMaxDynamicSharedMemorySize, SM_TOTAL);

    // GEMM1: ONE launch, K split via gridDim.z=2 (2000 CTAs in one grid ->
    // 6.76 waves, tail ~3.5% instead of 2 x 3.38-wave launches at 15% each).
    {
        dim3 grid(D_HID / 128, M / 128, 2);   // (8, 125, 2) = 2000 CTAs
        const int NKslice = (D_IN / 32) / 2;  // 196 iterations (even)
        gemm_f16s<0><<<grid, 256, SM_TOTAL>>>(X16, W1h, nullptr, h1p, partStride,
                                              D_IN, NKslice, D_HID);
    }

    // combine partials -> h1 fp16 (bias + relu)
    {
        const size_t n4 = (size_t)M * D_HID / 4;
        combine_h1<<<(unsigned)((n4 + 255) / 256), 256>>>(h1p, h1p + partStride, b1, h1, n4);
    }

    // GEMM2: single product fp16, bias + relu -> fp32 h2
    {
        dim3 grid(D_HID / 128, M / 128, 1);   // 1000 CTAs
        gemm_f16s<1><<<grid, 256, SM_TOTAL>>>(h1, W2h, b2, h2, 0,
                                              D_HID, D_HID / 32, D_HID);
    }

    const int threads = 256;
    const int blocks = (M * 32 + threads - 1) / threads;
    heads_kernel<<<blocks, threads>>>(h2, Wc, bc, Wr, br, out, M);
}